// round 7
// baseline (speedup 1.0000x reference)
#include <cuda_runtime.h>
#include <cuda_bf16.h>
#include <cstdint>

#define N_NODES 100000
#define N_EDGES 1600000
#define HID 64
#define NGROUPS (N_EDGES / 32)       // 50000
#define NODE_GROUPS (N_NODES / 32)   // 3125

typedef unsigned long long ull;

// ---------- device scratch ----------
__device__ float g_h[N_NODES * HID];
__device__ float g_agg[N_NODES * HID];
__device__ float g_P[N_NODES * HID];
__device__ float g_Q[N_NODES * HID];
__device__ float g_xA[N_NODES * 3];
__device__ float g_xB[N_NODES * 3];

// ---------- helpers ----------
__device__ __forceinline__ ull ffma2(ull a, ull b, ull c) {
    ull d;
    asm("fma.rn.f32x2 %0, %1, %2, %3;" : "=l"(d) : "l"(a), "l"(b), "l"(c));
    return d;
}
__device__ __forceinline__ ull pack2(float x, float y) {
    ull r; asm("mov.b64 %0, {%1, %2};" : "=l"(r) : "f"(x), "f"(y)); return r;
}
__device__ __forceinline__ float2 unpack2(ull v) {
    float2 r; asm("mov.b64 {%0, %1}, %2;" : "=f"(r.x), "=f"(r.y) : "l"(v)); return r;
}
// silu via tanh.approx (1 MUFU instead of 2)
__device__ __forceinline__ float silu(float v) {
    float u = 0.5f * v, th;
    asm("tanh.approx.f32 %0, %1;" : "=f"(th) : "f"(u));
    return v * fmaf(th, 0.5f, 0.5f);
}
__device__ __forceinline__ void red_add_v2(float* addr, float a, float b) {
    asm volatile("red.global.add.v2.f32 [%0], {%1, %2};"
                 :: "l"(addr), "f"(a), "f"(b) : "memory");
}
// packed bf16 split: hi = bf16x2(f1,f0), lo = bf16x2(residuals)
__device__ __forceinline__ void bf16_split2(float f0, float f1, uint32_t& hi, uint32_t& lo) {
    uint32_t h;
    asm("cvt.rn.bf16x2.f32 %0, %1, %2;" : "=r"(h) : "f"(f1), "f"(f0));
    float h0 = __uint_as_float(h << 16);
    float h1 = __uint_as_float(h & 0xffff0000u);
    float l0 = f0 - h0, l1 = f1 - h1;
    uint32_t l;
    asm("cvt.rn.bf16x2.f32 %0, %1, %2;" : "=r"(l) : "f"(l1), "f"(l0));
    hi = h; lo = l;
}
// mma.sync m16n8k16 bf16 -> f32, accumulate in place
__device__ __forceinline__ void mma16816(float c[4], const uint32_t a[4],
                                         uint32_t b0, uint32_t b1) {
    asm volatile(
        "mma.sync.aligned.m16n8k16.row.col.f32.bf16.bf16.f32 "
        "{%0,%1,%2,%3}, {%4,%5,%6,%7}, {%8,%9}, {%0,%1,%2,%3};"
        : "+f"(c[0]), "+f"(c[1]), "+f"(c[2]), "+f"(c[3])
        : "r"(a[0]), "r"(a[1]), "r"(a[2]), "r"(a[3]), "r"(b0), "r"(b1));
}

// ---------- init ----------
__global__ void init_kernel(const int* __restrict__ z, const float* __restrict__ emb,
                            const float* __restrict__ t,
                            const float* __restrict__ tw1, const float* __restrict__ tb1,
                            const float* __restrict__ tw2, const float* __restrict__ tb2,
                            int B) {
    __shared__ float s1[HID];
    __shared__ float tm[HID];
    int tidb = threadIdx.x;
    if (tidb < HID) {
        float w = tw1[tidb], bb = tb1[tidb];
        float acc = 0.f;
        for (int b = 0; b < B; b++) acc += silu(t[b] * w + bb);
        s1[tidb] = acc / (float)B;
    }
    __syncthreads();
    if (tidb < HID) {
        float o = tb2[tidb];
        for (int k = 0; k < HID; k++) o += s1[k] * tw2[k * HID + tidb];
        tm[tidb] = o;
    }
    __syncthreads();
    int i = blockIdx.x * blockDim.x + tidb;
    if (i < N_NODES * HID) {
        int node = i >> 6, j = i & 63;
        g_h[i] = emb[z[node] * HID + j] + tm[j];
        g_agg[i] = 0.f;
    }
}

// ---------- SIMT matmul helpers for node kernel ----------
__device__ __forceinline__ void mm_pass16(const float* __restrict__ frow,
                                          const ulonglong2* __restrict__ W,
                                          ull acc[16]) {
    #pragma unroll 4
    for (int k = 0; k < 64; k++) {
        float f = frow[k];
        ull fd = pack2(f, f);
        #pragma unroll
        for (int q = 0; q < 8; q++) {
            ulonglong2 wv = W[k * 16 + q];
            acc[2 * q]     = ffma2(fd, wv.x, acc[2 * q]);
            acc[2 * q + 1] = ffma2(fd, wv.y, acc[2 * q + 1]);
        }
    }
}
__device__ __forceinline__ void stage_quad(float* dst, const float* __restrict__ src,
                                           int rows, int tid, int nthreads) {
    for (int i = tid; i < rows * 64; i += nthreads) {
        int k = i >> 6, c = i & 63, q = c >> 2, r = c & 3;
        int j = 2 * q + (r >> 1) + ((r & 1) << 5);
        dst[i] = src[k * 64 + j];
    }
}

// ---------- pre kernel (mma.sync): P = h@W1a + b1, Q = h@W1b ----------
// smem words
#define PW_AH 0
#define PW_AL 2304
#define PW_BH 4608
#define PW_BL 6912
#define P_B1W 9216
#define P_WBASE 9280
#define P_WW 2304             // Ah 1152 + Al 1152
#define P_SMEM_WORDS (P_WBASE + 6 * P_WW)
#define P_SMEM_BYTES (P_SMEM_WORDS * 4)   // 92,416 B -> 2 CTAs/SM

__global__ void __launch_bounds__(192)
pre_kernel(const float* __restrict__ ew1, const float* __restrict__ eb1g) {
    extern __shared__ uint32_t smw[];
    float* smf = (float*)smw;
    const int tid = threadIdx.x;

    for (int i = tid; i < 2048; i += 192) {
        int n = i >> 5, kk = i & 31;
        uint32_t hi, lo;
        bf16_split2(ew1[(2 * kk) * 64 + n], ew1[(2 * kk + 1) * 64 + n], hi, lo);
        smw[PW_AH + n * 36 + kk] = hi;
        smw[PW_AL + n * 36 + kk] = lo;
        bf16_split2(ew1[(64 + 2 * kk) * 64 + n], ew1[(64 + 2 * kk + 1) * 64 + n], hi, lo);
        smw[PW_BH + n * 36 + kk] = hi;
        smw[PW_BL + n * 36 + kk] = lo;
    }
    if (tid < 64) smf[P_B1W + tid] = eb1g[tid];
    __syncthreads();

    const int lane = tid & 31;
    const int wrp = tid >> 5;
    const int g = lane >> 2;
    const int t = lane & 3;
    uint32_t* Ah = smw + P_WBASE + wrp * P_WW;
    uint32_t* Al = Ah + 1152;

    const int gwarp = (blockIdx.x * 192 + tid) >> 5;
    const int nwarps = (gridDim.x * 192) >> 5;

    for (int grp = gwarp; grp < NODE_GROUPS; grp += nwarps) {
        const int base = grp * 32;
        __syncwarp();
        #pragma unroll 4
        for (int e2 = 0; e2 < 32; e2++) {
            float2 hv = __ldg((const float2*)(g_h + (size_t)(base + e2) * 64 + 2 * lane));
            uint32_t hi, lo;
            bf16_split2(hv.x, hv.y, hi, lo);
            Ah[e2 * 36 + lane] = hi;
            Al[e2 * 36 + lane] = lo;
        }
        __syncwarp();

        float accP[16][4], accQ[16][4];
        #pragma unroll
        for (int nt = 0; nt < 8; nt++) {
            float2 bb = *(const float2*)(smf + P_B1W + 8 * nt + 2 * t);
            #pragma unroll
            for (int mt = 0; mt < 2; mt++) {
                accP[mt * 8 + nt][0] = bb.x; accP[mt * 8 + nt][1] = bb.y;
                accP[mt * 8 + nt][2] = bb.x; accP[mt * 8 + nt][3] = bb.y;
                accQ[mt * 8 + nt][0] = 0.f; accQ[mt * 8 + nt][1] = 0.f;
                accQ[mt * 8 + nt][2] = 0.f; accQ[mt * 8 + nt][3] = 0.f;
            }
        }
        #pragma unroll
        for (int kt = 0; kt < 4; kt++) {
            uint32_t ah[2][4], al[2][4];
            #pragma unroll
            for (int mt = 0; mt < 2; mt++) {
                int rb = (16 * mt + g) * 36 + 8 * kt + t;
                ah[mt][0] = Ah[rb];     ah[mt][1] = Ah[rb + 8 * 36];
                ah[mt][2] = Ah[rb + 4]; ah[mt][3] = Ah[rb + 8 * 36 + 4];
                al[mt][0] = Al[rb];     al[mt][1] = Al[rb + 8 * 36];
                al[mt][2] = Al[rb + 4]; al[mt][3] = Al[rb + 8 * 36 + 4];
            }
            #pragma unroll
            for (int nt = 0; nt < 8; nt++) {
                int bi = (8 * nt + g) * 36 + 8 * kt + t;
                uint32_t ah0 = smw[PW_AH + bi], ah1 = smw[PW_AH + bi + 4];
                uint32_t al0 = smw[PW_AL + bi], al1 = smw[PW_AL + bi + 4];
                uint32_t bh0 = smw[PW_BH + bi], bh1 = smw[PW_BH + bi + 4];
                uint32_t bl0 = smw[PW_BL + bi], bl1 = smw[PW_BL + bi + 4];
                #pragma unroll
                for (int mt = 0; mt < 2; mt++) {
                    mma16816(accP[mt * 8 + nt], ah[mt], ah0, ah1);
                    mma16816(accP[mt * 8 + nt], ah[mt], al0, al1);
                    mma16816(accP[mt * 8 + nt], al[mt], ah0, ah1);
                    mma16816(accQ[mt * 8 + nt], ah[mt], bh0, bh1);
                    mma16816(accQ[mt * 8 + nt], ah[mt], bl0, bl1);
                    mma16816(accQ[mt * 8 + nt], al[mt], bh0, bh1);
                }
            }
        }
        #pragma unroll
        for (int mt = 0; mt < 2; mt++) {
            int r1 = base + 16 * mt + g;
            int r2 = r1 + 8;
            #pragma unroll
            for (int nt = 0; nt < 8; nt++) {
                int c = 8 * nt + 2 * t;
                *(float2*)(g_P + (size_t)r1 * 64 + c) = make_float2(accP[mt * 8 + nt][0], accP[mt * 8 + nt][1]);
                *(float2*)(g_P + (size_t)r2 * 64 + c) = make_float2(accP[mt * 8 + nt][2], accP[mt * 8 + nt][3]);
                *(float2*)(g_Q + (size_t)r1 * 64 + c) = make_float2(accQ[mt * 8 + nt][0], accQ[mt * 8 + nt][1]);
                *(float2*)(g_Q + (size_t)r2 * 64 + c) = make_float2(accQ[mt * 8 + nt][2], accQ[mt * 8 + nt][3]);
            }
        }
    }
}

// ---------- edge kernel (mma.sync bf16-split) ----------
#define B_W2HI 0
#define B_W2LO 2304
#define B_C1HI 4608
#define B_C1LO 6912
#define SC_W1C 9216
#define SC_B2  9280
#define SC_CB1 9344
#define SC_CW2 9408
#define SC_CB2 9472
#define WARP_BASE 9480
#define WARP_W 2496          // idx/dx/r2 (192) + Ahi 1152 + Alo 1152
#define EDGE_SMEM_WORDS (WARP_BASE + 6 * WARP_W)
#define EDGE_SMEM_BYTES (EDGE_SMEM_WORDS * 4)   // 97,824 B -> 2 CTAs/SM

__global__ void __launch_bounds__(192)
edge_kernel(const float* __restrict__ x, float* __restrict__ xn,
            const int* __restrict__ ei,
            const float* __restrict__ w1c_g,
            const float* __restrict__ ew2, const float* __restrict__ eb2g,
            const float* __restrict__ cw1, const float* __restrict__ cb1g,
            const float* __restrict__ cw2g, const float* __restrict__ cb2g,
            int do_agg) {
    extern __shared__ uint32_t smw[];
    float* smf = (float*)smw;
    const int tid = threadIdx.x;

    for (int i = tid; i < 2048; i += 192) {
        int n = i >> 5, kk = i & 31;
        uint32_t hi, lo;
        bf16_split2(ew2[(2 * kk) * 64 + n], ew2[(2 * kk + 1) * 64 + n], hi, lo);
        smw[B_W2HI + n * 36 + kk] = hi;
        smw[B_W2LO + n * 36 + kk] = lo;
        bf16_split2(cw1[(2 * kk) * 64 + n], cw1[(2 * kk + 1) * 64 + n], hi, lo);
        smw[B_C1HI + n * 36 + kk] = hi;
        smw[B_C1LO + n * 36 + kk] = lo;
    }
    if (tid < 64) {
        smf[SC_W1C + tid] = w1c_g[tid];
        smf[SC_B2 + tid]  = eb2g[tid];
        smf[SC_CB1 + tid] = cb1g[tid];
        smf[SC_CW2 + tid] = cw2g[tid];
    }
    if (tid == 0) smf[SC_CB2] = cb2g[0];
    __syncthreads();

    const int lane = tid & 31;
    const int wrp = tid >> 5;
    const int g = lane >> 2;
    const int t = lane & 3;
    uint32_t* wb = smw + WARP_BASE + wrp * WARP_W;
    int* idxd = (int*)wb;
    int* idxs = idxd + 32;
    float* sdx0 = (float*)(wb + 64);
    float* sdx1 = (float*)(wb + 96);
    float* sdx2 = (float*)(wb + 128);
    float* sr2  = (float*)(wb + 160);
    uint32_t* Ah = wb + 192;
    uint32_t* Al = Ah + 1152;
    const float w1c0 = smf[SC_W1C + 2 * lane];
    const float w1c1 = smf[SC_W1C + 2 * lane + 1];
    const float cb2s = smf[SC_CB2];

    const int gwarp = (blockIdx.x * 192 + tid) >> 5;
    const int nwarps = (gridDim.x * 192) >> 5;

    for (int grp = gwarp; grp < NGROUPS; grp += nwarps) {
        const int e = grp * 32 + lane;
        const int s = ei[e];
        const int d = ei[N_EDGES + e];
        const float dx0 = __ldg(&x[d * 3 + 0]) - __ldg(&x[s * 3 + 0]);
        const float dx1 = __ldg(&x[d * 3 + 1]) - __ldg(&x[s * 3 + 1]);
        const float dx2 = __ldg(&x[d * 3 + 2]) - __ldg(&x[s * 3 + 2]);
        const float r2 = dx0 * dx0 + dx1 * dx1 + dx2 * dx2;
        __syncwarp();
        idxd[lane] = d; idxs[lane] = s;
        sdx0[lane] = dx0; sdx1[lane] = dx1; sdx2[lane] = dx2; sr2[lane] = r2;
        __syncwarp();

        // ---- features: silu(P[d]+Q[s]+r2*w1c) -> bf16 hi/lo A smem ----
        #pragma unroll 4
        for (int e2 = 0; e2 < 32; e2++) {
            int nd = idxd[e2], ns = idxs[e2];
            float rr = sr2[e2];
            float2 pv = __ldg((const float2*)(g_P + (size_t)nd * 64 + 2 * lane));
            float2 qv = __ldg((const float2*)(g_Q + (size_t)ns * 64 + 2 * lane));
            float f0 = silu(fmaf(rr, w1c0, pv.x + qv.x));
            float f1 = silu(fmaf(rr, w1c1, pv.y + qv.y));
            uint32_t hi, lo;
            bf16_split2(f0, f1, hi, lo);
            Ah[e2 * 36 + lane] = hi;
            Al[e2 * 36 + lane] = lo;
        }
        __syncwarp();

        // ---- matmul1: D = ef1 @ W2 + b2 ----
        float acc[16][4];
        #pragma unroll
        for (int nt = 0; nt < 8; nt++) {
            float2 bb = *(const float2*)(smf + SC_B2 + 8 * nt + 2 * t);
            #pragma unroll
            for (int mt = 0; mt < 2; mt++) {
                acc[mt * 8 + nt][0] = bb.x; acc[mt * 8 + nt][1] = bb.y;
                acc[mt * 8 + nt][2] = bb.x; acc[mt * 8 + nt][3] = bb.y;
            }
        }
        #pragma unroll
        for (int kt = 0; kt < 4; kt++) {
            uint32_t ah[2][4], al[2][4];
            #pragma unroll
            for (int mt = 0; mt < 2; mt++) {
                int rb = (16 * mt + g) * 36 + 8 * kt + t;
                ah[mt][0] = Ah[rb];     ah[mt][1] = Ah[rb + 8 * 36];
                ah[mt][2] = Ah[rb + 4]; ah[mt][3] = Ah[rb + 8 * 36 + 4];
                al[mt][0] = Al[rb];     al[mt][1] = Al[rb + 8 * 36];
                al[mt][2] = Al[rb + 4]; al[mt][3] = Al[rb + 8 * 36 + 4];
            }
            #pragma unroll
            for (int nt = 0; nt < 8; nt++) {
                int bi = (8 * nt + g) * 36 + 8 * kt + t;
                uint32_t bh0 = smw[B_W2HI + bi], bh1 = smw[B_W2HI + bi + 4];
                uint32_t bl0 = smw[B_W2LO + bi], bl1 = smw[B_W2LO + bi + 4];
                #pragma unroll
                for (int mt = 0; mt < 2; mt++) {
                    mma16816(acc[mt * 8 + nt], ah[mt], bh0, bh1);
                    mma16816(acc[mt * 8 + nt], ah[mt], bl0, bl1);
                    mma16816(acc[mt * 8 + nt], al[mt], bh0, bh1);
                }
            }
        }

        // ---- m = silu(D); agg red.v2; in-register to matmul2 A fragments ----
        uint32_t mh[2][4][4], ml[2][4][4];
        int dtop[2], dbot[2];
        #pragma unroll
        for (int mt = 0; mt < 2; mt++) {
            dtop[mt] = idxd[16 * mt + g];
            dbot[mt] = idxd[16 * mt + g + 8];
        }
        #pragma unroll
        for (int mt = 0; mt < 2; mt++) {
            #pragma unroll
            for (int nt = 0; nt < 8; nt++) {
                float v0 = silu(acc[mt * 8 + nt][0]);
                float v1 = silu(acc[mt * 8 + nt][1]);
                float v2 = silu(acc[mt * 8 + nt][2]);
                float v3 = silu(acc[mt * 8 + nt][3]);
                if (do_agg) {
                    red_add_v2(&g_agg[(size_t)dtop[mt] * 64 + 8 * nt + 2 * t], v0, v1);
                    red_add_v2(&g_agg[(size_t)dbot[mt] * 64 + 8 * nt + 2 * t], v2, v3);
                }
                int kt = nt >> 1, o = (nt & 1) * 2;
                bf16_split2(v0, v1, mh[mt][kt][o], ml[mt][kt][o]);
                bf16_split2(v2, v3, mh[mt][kt][o + 1], ml[mt][kt][o + 1]);
            }
        }

        // ---- matmul2: D2 = m @ C1 + cb1 ----
        float acc2[16][4];
        #pragma unroll
        for (int nt = 0; nt < 8; nt++) {
            float2 bb = *(const float2*)(smf + SC_CB1 + 8 * nt + 2 * t);
            #pragma unroll
            for (int mt = 0; mt < 2; mt++) {
                acc2[mt * 8 + nt][0] = bb.x; acc2[mt * 8 + nt][1] = bb.y;
                acc2[mt * 8 + nt][2] = bb.x; acc2[mt * 8 + nt][3] = bb.y;
            }
        }
        #pragma unroll
        for (int kt = 0; kt < 4; kt++) {
            #pragma unroll
            for (int nt = 0; nt < 8; nt++) {
                int bi = (8 * nt + g) * 36 + 8 * kt + t;
                uint32_t bh0 = smw[B_C1HI + bi], bh1 = smw[B_C1HI + bi + 4];
                uint32_t bl0 = smw[B_C1LO + bi], bl1 = smw[B_C1LO + bi + 4];
                #pragma unroll
                for (int mt = 0; mt < 2; mt++) {
                    mma16816(acc2[mt * 8 + nt], mh[mt][kt], bh0, bh1);
                    mma16816(acc2[mt * 8 + nt], mh[mt][kt], bl0, bl1);
                    mma16816(acc2[mt * 8 + nt], ml[mt][kt], bh0, bh1);
                }
            }
        }

        // ---- coord epilogue ----
        float pr0 = 0.f, pr1 = 0.f, pr2 = 0.f, pr3 = 0.f;
        #pragma unroll
        for (int nt = 0; nt < 8; nt++) {
            float2 cwv = *(const float2*)(smf + SC_CW2 + 8 * nt + 2 * t);
            pr0 = fmaf(silu(acc2[nt][0]), cwv.x, pr0);
            pr0 = fmaf(silu(acc2[nt][1]), cwv.y, pr0);
            pr1 = fmaf(silu(acc2[nt][2]), cwv.x, pr1);
            pr1 = fmaf(silu(acc2[nt][3]), cwv.y, pr1);
            pr2 = fmaf(silu(acc2[8 + nt][0]), cwv.x, pr2);
            pr2 = fmaf(silu(acc2[8 + nt][1]), cwv.y, pr2);
            pr3 = fmaf(silu(acc2[8 + nt][2]), cwv.x, pr3);
            pr3 = fmaf(silu(acc2[8 + nt][3]), cwv.y, pr3);
        }
        pr0 += __shfl_xor_sync(0xffffffffu, pr0, 1);
        pr0 += __shfl_xor_sync(0xffffffffu, pr0, 2);
        pr1 += __shfl_xor_sync(0xffffffffu, pr1, 1);
        pr1 += __shfl_xor_sync(0xffffffffu, pr1, 2);
        pr2 += __shfl_xor_sync(0xffffffffu, pr2, 1);
        pr2 += __shfl_xor_sync(0xffffffffu, pr2, 2);
        pr3 += __shfl_xor_sync(0xffffffffu, pr3, 1);
        pr3 += __shfl_xor_sync(0xffffffffu, pr3, 2);
        float p = (t == 0) ? pr0 : (t == 1) ? pr1 : (t == 2) ? pr2 : pr3;
        int e2 = g + 8 * t;
        p += cb2s;
        int dd = idxd[e2];
        atomicAdd(&xn[dd * 3 + 0], sdx0[e2] * p);
        atomicAdd(&xn[dd * 3 + 1], sdx1[e2] * p);
        atomicAdd(&xn[dd * 3 + 2], sdx2[e2] * p);
    }
}

// ---------- node kernel (SIMT, tanh silu) ----------
#define ND_W1   0
#define ND_W2   8192
#define ND_B1   12288
#define ND_B2   12352
#define ND_WARP 12416
#define ND_PW   (32 * 65)
#define ND_SMEMF (ND_WARP + 16 * ND_PW)
#define NSMEM_BYTES (ND_SMEMF * 4)

__global__ void __launch_bounds__(512, 1)
node_kernel(const float* __restrict__ nw1, const float* __restrict__ nb1g,
            const float* __restrict__ nw2, const float* __restrict__ nb2g) {
    extern __shared__ float sm[];
    const int tid = threadIdx.x;
    stage_quad(sm + ND_W1, nw1, 128, tid, 512);
    stage_quad(sm + ND_W2, nw2, 64, tid, 512);
    if (tid < 32) {
        sm[ND_B1 + 2 * tid] = nb1g[tid]; sm[ND_B1 + 2 * tid + 1] = nb1g[tid + 32];
        sm[ND_B2 + 2 * tid] = nb2g[tid]; sm[ND_B2 + 2 * tid + 1] = nb2g[tid + 32];
    }
    __syncthreads();

    const int lane = tid & 31, wrp = tid >> 5;
    float* fb = sm + ND_WARP + wrp * ND_PW;
    float* frow = fb + lane * 65;
    const ulonglong2* W1v = (const ulonglong2*)(sm + ND_W1);
    const ulonglong2* W2v = (const ulonglong2*)(sm + ND_W2);
    const ull* B1 = (const ull*)(sm + ND_B1);
    const ull* B2 = (const ull*)(sm + ND_B2);

    int gw = (blockIdx.x * 512 + tid) >> 5;
    int nwrp = (gridDim.x * 512) >> 5;
    for (int g = gw; g < NODE_GROUPS; g += nwrp) {
        const int base = g * 32;
        ull acc[16];
        float mlo[16], mhi[16];
        #pragma unroll
        for (int a = 0; a < 16; a++) acc[a] = B1[a];
        __syncwarp();
        #pragma unroll 4
        for (int e2 = 0; e2 < 32; e2++) {
            float2 hv = *(const float2*)(g_h + (size_t)(base + e2) * 64 + 2 * lane);
            fb[e2 * 65 + 2 * lane] = hv.x; fb[e2 * 65 + 2 * lane + 1] = hv.y;
        }
        __syncwarp();
        mm_pass16(frow, W1v, acc);
        __syncwarp();
        #pragma unroll 4
        for (int e2 = 0; e2 < 32; e2++) {
            float2 av = *(const float2*)(g_agg + (size_t)(base + e2) * 64 + 2 * lane);
            fb[e2 * 65 + 2 * lane] = av.x; fb[e2 * 65 + 2 * lane + 1] = av.y;
        }
        __syncwarp();
        mm_pass16(frow, W1v + 64 * 16, acc);
        #pragma unroll
        for (int a = 0; a < 16; a++) {
            float2 v = unpack2(acc[a]);
            mlo[a] = silu(v.x); mhi[a] = silu(v.y);
        }
        #pragma unroll
        for (int a = 0; a < 16; a++) acc[a] = B1[16 + a];
        __syncwarp();
        #pragma unroll 4
        for (int e2 = 0; e2 < 32; e2++) {
            float2 hv = *(const float2*)(g_h + (size_t)(base + e2) * 64 + 2 * lane);
            fb[e2 * 65 + 2 * lane] = hv.x; fb[e2 * 65 + 2 * lane + 1] = hv.y;
        }
        __syncwarp();
        mm_pass16(frow, W1v + 8, acc);
        __syncwarp();
        #pragma unroll 4
        for (int e2 = 0; e2 < 32; e2++) {
            float2 av = *(const float2*)(g_agg + (size_t)(base + e2) * 64 + 2 * lane);
            fb[e2 * 65 + 2 * lane] = av.x; fb[e2 * 65 + 2 * lane + 1] = av.y;
        }
        __syncwarp();
        mm_pass16(frow, W1v + 64 * 16 + 8, acc);
        #pragma unroll
        for (int a = 0; a < 16; a++) {
            float2 v = unpack2(acc[a]);
            frow[16 + a] = silu(v.x); frow[48 + a] = silu(v.y);
        }
        #pragma unroll
        for (int a = 0; a < 16; a++) { frow[a] = mlo[a]; frow[32 + a] = mhi[a]; }

        float* hrow = g_h + (size_t)(base + lane) * 64;
        float* arow = g_agg + (size_t)(base + lane) * 64;
        #pragma unroll
        for (int pass = 0; pass < 2; pass++) {
            #pragma unroll
            for (int a = 0; a < 16; a++) acc[a] = B2[16 * pass + a];
            mm_pass16(frow, W2v + 8 * pass, acc);
            #pragma unroll
            for (int t4 = 0; t4 < 4; t4++) {
                float2 v0 = unpack2(acc[4 * t4 + 0]);
                float2 v1 = unpack2(acc[4 * t4 + 1]);
                float2 v2 = unpack2(acc[4 * t4 + 2]);
                float2 v3 = unpack2(acc[4 * t4 + 3]);
                float4 ho = *(const float4*)(hrow + 16 * pass + 4 * t4);
                ho.x += v0.x; ho.y += v1.x; ho.z += v2.x; ho.w += v3.x;
                *(float4*)(hrow + 16 * pass + 4 * t4) = ho;
                float4 hh = *(const float4*)(hrow + 16 * pass + 32 + 4 * t4);
                hh.x += v0.y; hh.y += v1.y; hh.z += v2.y; hh.w += v3.y;
                *(float4*)(hrow + 16 * pass + 32 + 4 * t4) = hh;
                *(float4*)(arow + 16 * pass + 4 * t4) = make_float4(0.f, 0.f, 0.f, 0.f);
                *(float4*)(arow + 16 * pass + 32 + 4 * t4) = make_float4(0.f, 0.f, 0.f, 0.f);
            }
        }
    }
}

// ---------- launch ----------
extern "C" void kernel_launch(void* const* d_in, const int* in_sizes, int n_in,
                              void* d_out, int out_size) {
    const float* x   = (const float*)d_in[0];
    const int*   z   = (const int*)d_in[1];
    const float* t   = (const float*)d_in[2];
    const int*   ei  = (const int*)d_in[3];
    const float* emb = (const float*)d_in[4];
    const float* tw1 = (const float*)d_in[5];
    const float* tb1 = (const float*)d_in[6];
    const float* tw2 = (const float*)d_in[7];
    const float* tb2 = (const float*)d_in[8];
    const float* ew1 = (const float*)d_in[9];
    const float* eb1 = (const float*)d_in[10];
    const float* ew2 = (const float*)d_in[11];
    const float* eb2 = (const float*)d_in[12];
    const float* cw1 = (const float*)d_in[13];
    const float* cb1 = (const float*)d_in[14];
    const float* cw2 = (const float*)d_in[15];
    const float* cb2 = (const float*)d_in[16];
    const float* nw1 = (const float*)d_in[17];
    const float* nb1 = (const float*)d_in[18];
    const float* nw2 = (const float*)d_in[19];
    const float* nb2 = (const float*)d_in[20];
    float* out = (float*)d_out;
    const int B = in_sizes[2];

    float *pxA, *pxB;
    cudaGetSymbolAddress((void**)&pxA, g_xA);
    cudaGetSymbolAddress((void**)&pxB, g_xB);

    cudaFuncSetAttribute(edge_kernel, cudaFuncAttributeMaxDynamicSharedMemorySize, EDGE_SMEM_BYTES);
    cudaFuncSetAttribute(node_kernel, cudaFuncAttributeMaxDynamicSharedMemorySize, NSMEM_BYTES);
    cudaFuncSetAttribute(pre_kernel,  cudaFuncAttributeMaxDynamicSharedMemorySize, P_SMEM_BYTES);

    const size_t XB = (size_t)N_NODES * 3 * sizeof(float);
    const int EGRID = 304;   // 2 CTAs/SM x 152
    const int PGRID = 304;

    init_kernel<<<(N_NODES * HID + 255) / 256, 256>>>(z, emb, t, tw1, tb1, tw2, tb2, B);

    // ---- layer 0 ----
    pre_kernel<<<PGRID, 192, P_SMEM_BYTES>>>(ew1 + 0 * 129 * 64, eb1 + 0 * 64);
    cudaMemcpyAsync(pxB, x, XB, cudaMemcpyDeviceToDevice, 0);
    edge_kernel<<<EGRID, 192, EDGE_SMEM_BYTES>>>(x, pxB, ei,
        ew1 + 0 * 129 * 64 + 128 * 64, ew2 + 0 * 4096, eb2 + 0 * 64,
        cw1 + 0 * 4096, cb1 + 0 * 64, cw2 + 0 * 64, cb2 + 0, 1);
    node_kernel<<<152, 512, NSMEM_BYTES>>>(nw1 + 0 * 128 * 64, nb1 + 0 * 64,
                                           nw2 + 0 * 4096, nb2 + 0 * 64);

    // ---- layer 1 ----
    pre_kernel<<<PGRID, 192, P_SMEM_BYTES>>>(ew1 + 1 * 129 * 64, eb1 + 1 * 64);
    cudaMemcpyAsync(pxA, pxB, XB, cudaMemcpyDeviceToDevice, 0);
    edge_kernel<<<EGRID, 192, EDGE_SMEM_BYTES>>>(pxB, pxA, ei,
        ew1 + 1 * 129 * 64 + 128 * 64, ew2 + 1 * 4096, eb2 + 1 * 64,
        cw1 + 1 * 4096, cb1 + 1 * 64, cw2 + 1 * 64, cb2 + 1, 1);
    node_kernel<<<152, 512, NSMEM_BYTES>>>(nw1 + 1 * 128 * 64, nb1 + 1 * 64,
                                           nw2 + 1 * 4096, nb2 + 1 * 64);

    // ---- layer 2: agg/node dead, write x' straight to d_out ----
    pre_kernel<<<PGRID, 192, P_SMEM_BYTES>>>(ew1 + 2 * 129 * 64, eb1 + 2 * 64);
    cudaMemcpyAsync(out, pxA, XB, cudaMemcpyDeviceToDevice, 0);
    edge_kernel<<<EGRID, 192, EDGE_SMEM_BYTES>>>(pxA, out, ei,
        ew1 + 2 * 129 * 64 + 128 * 64, ew2 + 2 * 4096, eb2 + 2 * 64,
        cw1 + 2 * 4096, cb1 + 2 * 64, cw2 + 2 * 64, cb2 + 2, 0);
}

// round 8
// speedup vs baseline: 1.6175x; 1.6175x over previous
#include <cuda_runtime.h>
#include <cuda_bf16.h>
#include <cstdint>

#define N_NODES 100000
#define N_EDGES 1600000
#define HID 64
#define NGROUPS (N_EDGES / 32)       // 50000
#define NODE_GROUPS (N_NODES / 32)   // 3125

typedef unsigned long long ull;

// ---------- device scratch ----------
__device__ float g_h[N_NODES * HID];
__device__ float g_agg[N_NODES * HID];
__device__ float g_P[N_NODES * HID];
__device__ float g_Q[N_NODES * HID];
__device__ float g_xA[N_NODES * 3];
__device__ float g_xB[N_NODES * 3];

// ---------- helpers ----------
__device__ __forceinline__ ull ffma2(ull a, ull b, ull c) {
    ull d;
    asm("fma.rn.f32x2 %0, %1, %2, %3;" : "=l"(d) : "l"(a), "l"(b), "l"(c));
    return d;
}
__device__ __forceinline__ ull pack2(float x, float y) {
    ull r; asm("mov.b64 %0, {%1, %2};" : "=l"(r) : "f"(x), "f"(y)); return r;
}
__device__ __forceinline__ float2 unpack2(ull v) {
    float2 r; asm("mov.b64 {%0, %1}, %2;" : "=f"(r.x), "=f"(r.y) : "l"(v)); return r;
}
// silu via tanh.approx (1 MUFU)
__device__ __forceinline__ float silu(float v) {
    float u = 0.5f * v, th;
    asm("tanh.approx.f32 %0, %1;" : "=f"(th) : "f"(u));
    return v * fmaf(th, 0.5f, 0.5f);
}
__device__ __forceinline__ void red_add_v4(float* addr, float a, float b, float c, float d) {
    asm volatile("red.global.add.v4.f32 [%0], {%1, %2, %3, %4};"
                 :: "l"(addr), "f"(a), "f"(b), "f"(c), "f"(d) : "memory");
}
// packed bf16 split
__device__ __forceinline__ void bf16_split2(float f0, float f1, uint32_t& hi, uint32_t& lo) {
    uint32_t h;
    asm("cvt.rn.bf16x2.f32 %0, %1, %2;" : "=r"(h) : "f"(f1), "f"(f0));
    float h0 = __uint_as_float(h << 16);
    float h1 = __uint_as_float(h & 0xffff0000u);
    float l0 = f0 - h0, l1 = f1 - h1;
    uint32_t l;
    asm("cvt.rn.bf16x2.f32 %0, %1, %2;" : "=r"(l) : "f"(l1), "f"(l0));
    hi = h; lo = l;
}
// mma.sync m16n8k16 bf16 -> f32
__device__ __forceinline__ void mma16816(float c[4], const uint32_t a[4],
                                         uint32_t b0, uint32_t b1) {
    asm volatile(
        "mma.sync.aligned.m16n8k16.row.col.f32.bf16.bf16.f32 "
        "{%0,%1,%2,%3}, {%4,%5,%6,%7}, {%8,%9}, {%0,%1,%2,%3};"
        : "+f"(c[0]), "+f"(c[1]), "+f"(c[2]), "+f"(c[3])
        : "r"(a[0]), "r"(a[1]), "r"(a[2]), "r"(a[3]), "r"(b0), "r"(b1));
}

// ---------- init ----------
__global__ void init_kernel(const int* __restrict__ z, const float* __restrict__ emb,
                            const float* __restrict__ t,
                            const float* __restrict__ tw1, const float* __restrict__ tb1,
                            const float* __restrict__ tw2, const float* __restrict__ tb2,
                            int B) {
    __shared__ float s1[HID];
    __shared__ float tm[HID];
    int tidb = threadIdx.x;
    if (tidb < HID) {
        float w = tw1[tidb], bb = tb1[tidb];
        float acc = 0.f;
        for (int b = 0; b < B; b++) acc += silu(t[b] * w + bb);
        s1[tidb] = acc / (float)B;
    }
    __syncthreads();
    if (tidb < HID) {
        float o = tb2[tidb];
        for (int k = 0; k < HID; k++) o += s1[k] * tw2[k * HID + tidb];
        tm[tidb] = o;
    }
    __syncthreads();
    int i = blockIdx.x * blockDim.x + tidb;
    if (i < N_NODES * HID) {
        int node = i >> 6, j = i & 63;
        g_h[i] = emb[z[node] * HID + j] + tm[j];
        g_agg[i] = 0.f;
    }
}

// ---------- SIMT matmul helpers for node kernel ----------
__device__ __forceinline__ void mm_pass16(const float* __restrict__ frow,
                                          const ulonglong2* __restrict__ W,
                                          ull acc[16]) {
    #pragma unroll 4
    for (int k = 0; k < 64; k++) {
        float f = frow[k];
        ull fd = pack2(f, f);
        #pragma unroll
        for (int q = 0; q < 8; q++) {
            ulonglong2 wv = W[k * 16 + q];
            acc[2 * q]     = ffma2(fd, wv.x, acc[2 * q]);
            acc[2 * q + 1] = ffma2(fd, wv.y, acc[2 * q + 1]);
        }
    }
}
__device__ __forceinline__ void stage_quad(float* dst, const float* __restrict__ src,
                                           int rows, int tid, int nthreads) {
    for (int i = tid; i < rows * 64; i += nthreads) {
        int k = i >> 6, c = i & 63, q = c >> 2, r = c & 3;
        int j = 2 * q + (r >> 1) + ((r & 1) << 5);
        dst[i] = src[k * 64 + j];
    }
}

// ---------- pre kernel (mma.sync): P = h@W1a + b1, Q = h@W1b ----------
#define PW_AH 0
#define PW_AL 2304
#define PW_BH 4608
#define PW_BL 6912
#define P_B1W 9216
#define P_WBASE 9280
#define P_WW 2304
#define P_SMEM_WORDS (P_WBASE + 6 * P_WW)
#define P_SMEM_BYTES (P_SMEM_WORDS * 4)

__global__ void __launch_bounds__(192)
pre_kernel(const float* __restrict__ ew1, const float* __restrict__ eb1g) {
    extern __shared__ uint32_t smw[];
    float* smf = (float*)smw;
    const int tid = threadIdx.x;

    for (int i = tid; i < 2048; i += 192) {
        int n = i >> 5, kk = i & 31;
        uint32_t hi, lo;
        bf16_split2(ew1[(2 * kk) * 64 + n], ew1[(2 * kk + 1) * 64 + n], hi, lo);
        smw[PW_AH + n * 36 + kk] = hi;
        smw[PW_AL + n * 36 + kk] = lo;
        bf16_split2(ew1[(64 + 2 * kk) * 64 + n], ew1[(64 + 2 * kk + 1) * 64 + n], hi, lo);
        smw[PW_BH + n * 36 + kk] = hi;
        smw[PW_BL + n * 36 + kk] = lo;
    }
    if (tid < 64) smf[P_B1W + tid] = eb1g[tid];
    __syncthreads();

    const int lane = tid & 31;
    const int wrp = tid >> 5;
    const int g = lane >> 2;
    const int t = lane & 3;
    uint32_t* Ah = smw + P_WBASE + wrp * P_WW;
    uint32_t* Al = Ah + 1152;

    const int gwarp = (blockIdx.x * 192 + tid) >> 5;
    const int nwarps = (gridDim.x * 192) >> 5;

    for (int grp = gwarp; grp < NODE_GROUPS; grp += nwarps) {
        const int base = grp * 32;
        __syncwarp();
        #pragma unroll 4
        for (int e2 = 0; e2 < 32; e2++) {
            float2 hv = __ldg((const float2*)(g_h + (size_t)(base + e2) * 64 + 2 * lane));
            uint32_t hi, lo;
            bf16_split2(hv.x, hv.y, hi, lo);
            Ah[e2 * 36 + lane] = hi;
            Al[e2 * 36 + lane] = lo;
        }
        __syncwarp();

        float accP[16][4], accQ[16][4];
        #pragma unroll
        for (int nt = 0; nt < 8; nt++) {
            float2 bb = *(const float2*)(smf + P_B1W + 8 * nt + 2 * t);
            #pragma unroll
            for (int mt = 0; mt < 2; mt++) {
                accP[mt * 8 + nt][0] = bb.x; accP[mt * 8 + nt][1] = bb.y;
                accP[mt * 8 + nt][2] = bb.x; accP[mt * 8 + nt][3] = bb.y;
                accQ[mt * 8 + nt][0] = 0.f; accQ[mt * 8 + nt][1] = 0.f;
                accQ[mt * 8 + nt][2] = 0.f; accQ[mt * 8 + nt][3] = 0.f;
            }
        }
        #pragma unroll
        for (int kt = 0; kt < 4; kt++) {
            uint32_t ah[2][4], al[2][4];
            #pragma unroll
            for (int mt = 0; mt < 2; mt++) {
                int rb = (16 * mt + g) * 36 + 8 * kt + t;
                ah[mt][0] = Ah[rb];     ah[mt][1] = Ah[rb + 8 * 36];
                ah[mt][2] = Ah[rb + 4]; ah[mt][3] = Ah[rb + 8 * 36 + 4];
                al[mt][0] = Al[rb];     al[mt][1] = Al[rb + 8 * 36];
                al[mt][2] = Al[rb + 4]; al[mt][3] = Al[rb + 8 * 36 + 4];
            }
            #pragma unroll
            for (int nt = 0; nt < 8; nt++) {
                int bi = (8 * nt + g) * 36 + 8 * kt + t;
                uint32_t ah0 = smw[PW_AH + bi], ah1 = smw[PW_AH + bi + 4];
                uint32_t al0 = smw[PW_AL + bi], al1 = smw[PW_AL + bi + 4];
                uint32_t bh0 = smw[PW_BH + bi], bh1 = smw[PW_BH + bi + 4];
                uint32_t bl0 = smw[PW_BL + bi], bl1 = smw[PW_BL + bi + 4];
                #pragma unroll
                for (int mt = 0; mt < 2; mt++) {
                    mma16816(accP[mt * 8 + nt], ah[mt], ah0, ah1);
                    mma16816(accP[mt * 8 + nt], ah[mt], al0, al1);
                    mma16816(accP[mt * 8 + nt], al[mt], ah0, ah1);
                    mma16816(accQ[mt * 8 + nt], ah[mt], bh0, bh1);
                    mma16816(accQ[mt * 8 + nt], ah[mt], bl0, bl1);
                    mma16816(accQ[mt * 8 + nt], al[mt], bh0, bh1);
                }
            }
        }
        #pragma unroll
        for (int mt = 0; mt < 2; mt++) {
            int r1 = base + 16 * mt + g;
            int r2 = r1 + 8;
            #pragma unroll
            for (int nt = 0; nt < 8; nt++) {
                int c = 8 * nt + 2 * t;
                *(float2*)(g_P + (size_t)r1 * 64 + c) = make_float2(accP[mt * 8 + nt][0], accP[mt * 8 + nt][1]);
                *(float2*)(g_P + (size_t)r2 * 64 + c) = make_float2(accP[mt * 8 + nt][2], accP[mt * 8 + nt][3]);
                *(float2*)(g_Q + (size_t)r1 * 64 + c) = make_float2(accQ[mt * 8 + nt][0], accQ[mt * 8 + nt][1]);
                *(float2*)(g_Q + (size_t)r2 * 64 + c) = make_float2(accQ[mt * 8 + nt][2], accQ[mt * 8 + nt][3]);
            }
        }
    }
}

// ---------- edge kernel (mma.sync, shfl idx, prefetch, red.v4) ----------
#define B_W2HI 0
#define B_W2LO 2304
#define B_C1HI 4608
#define B_C1LO 6912
#define SC_W1C 9216
#define SC_B2  9280
#define SC_CB1 9344
#define SC_CW2 9408
#define SC_CB2 9472
#define WARP_BASE 9480
#define WARP_W 2304          // Ah 1152 + Al 1152
#define EDGE_SMEM_WORDS (WARP_BASE + 4 * WARP_W)
#define EDGE_SMEM_BYTES (EDGE_SMEM_WORDS * 4)   // 74,784 B -> 2 CTAs/SM

__global__ void __launch_bounds__(128)
edge_kernel(const float* __restrict__ x, float* __restrict__ xn,
            const int* __restrict__ ei,
            const float* __restrict__ w1c_g,
            const float* __restrict__ ew2, const float* __restrict__ eb2g,
            const float* __restrict__ cw1, const float* __restrict__ cb1g,
            const float* __restrict__ cw2g, const float* __restrict__ cb2g,
            int do_agg) {
    extern __shared__ uint32_t smw[];
    float* smf = (float*)smw;
    const int tid = threadIdx.x;

    for (int i = tid; i < 2048; i += 128) {
        int n = i >> 5, kk = i & 31;
        uint32_t hi, lo;
        bf16_split2(ew2[(2 * kk) * 64 + n], ew2[(2 * kk + 1) * 64 + n], hi, lo);
        smw[B_W2HI + n * 36 + kk] = hi;
        smw[B_W2LO + n * 36 + kk] = lo;
        bf16_split2(cw1[(2 * kk) * 64 + n], cw1[(2 * kk + 1) * 64 + n], hi, lo);
        smw[B_C1HI + n * 36 + kk] = hi;
        smw[B_C1LO + n * 36 + kk] = lo;
    }
    if (tid < 64) {
        smf[SC_W1C + tid] = w1c_g[tid];
        smf[SC_B2 + tid]  = eb2g[tid];
        smf[SC_CB1 + tid] = cb1g[tid];
        smf[SC_CW2 + tid] = cw2g[tid];
    }
    if (tid == 0) smf[SC_CB2] = cb2g[0];
    __syncthreads();

    const int lane = tid & 31;
    const int wrp = tid >> 5;
    const int g = lane >> 2;
    const int t = lane & 3;
    uint32_t* Ah = smw + WARP_BASE + wrp * WARP_W;
    uint32_t* Al = Ah + 1152;
    const float w1c0 = smf[SC_W1C + 2 * lane];
    const float w1c1 = smf[SC_W1C + 2 * lane + 1];
    const float cb2s = smf[SC_CB2];

    const int gwarp = (blockIdx.x * 128 + tid) >> 5;
    const int nwarps = (gridDim.x * 128) >> 5;

    // prefetch first group
    int grp = gwarp;
    int s_n = 0, d_n = 0;
    float xs0 = 0, xs1 = 0, xs2 = 0, xd0 = 0, xd1 = 0, xd2 = 0;
    if (grp < NGROUPS) {
        int e = grp * 32 + lane;
        s_n = ei[e]; d_n = ei[N_EDGES + e];
        xs0 = __ldg(&x[s_n * 3 + 0]); xs1 = __ldg(&x[s_n * 3 + 1]); xs2 = __ldg(&x[s_n * 3 + 2]);
        xd0 = __ldg(&x[d_n * 3 + 0]); xd1 = __ldg(&x[d_n * 3 + 1]); xd2 = __ldg(&x[d_n * 3 + 2]);
    }

    for (; grp < NGROUPS; grp += nwarps) {
        const int s = s_n, d = d_n;
        const float dx0 = xd0 - xs0;
        const float dx1 = xd1 - xs1;
        const float dx2 = xd2 - xs2;
        const float r2 = dx0 * dx0 + dx1 * dx1 + dx2 * dx2;

        // ---- gather + phase1 fused (indices via shfl, no smem idx) ----
        __syncwarp();          // prior iteration done reading Ah/Al
        #pragma unroll 4
        for (int e2 = 0; e2 < 32; e2++) {
            int nd = __shfl_sync(0xffffffffu, d, e2);
            int ns = __shfl_sync(0xffffffffu, s, e2);
            float rr = __shfl_sync(0xffffffffu, r2, e2);
            float2 pv = __ldg((const float2*)(g_P + (size_t)nd * 64 + 2 * lane));
            float2 qv = __ldg((const float2*)(g_Q + (size_t)ns * 64 + 2 * lane));
            float f0 = silu(fmaf(rr, w1c0, pv.x + qv.x));
            float f1 = silu(fmaf(rr, w1c1, pv.y + qv.y));
            uint32_t hi, lo;
            bf16_split2(f0, f1, hi, lo);
            Ah[e2 * 36 + lane] = hi;
            Al[e2 * 36 + lane] = lo;
        }
        __syncwarp();

        // ---- prefetch next group (hide index->coord chain under matmuls) ----
        {
            int gn = grp + nwarps;
            if (gn < NGROUPS) {
                int e = gn * 32 + lane;
                s_n = ei[e]; d_n = ei[N_EDGES + e];
                xs0 = __ldg(&x[s_n * 3 + 0]); xs1 = __ldg(&x[s_n * 3 + 1]); xs2 = __ldg(&x[s_n * 3 + 2]);
                xd0 = __ldg(&x[d_n * 3 + 0]); xd1 = __ldg(&x[d_n * 3 + 1]); xd2 = __ldg(&x[d_n * 3 + 2]);
            }
        }

        // ---- matmul1: D = ef1 @ W2 + b2 ----
        float acc[16][4];
        #pragma unroll
        for (int nt = 0; nt < 8; nt++) {
            float2 bb = *(const float2*)(smf + SC_B2 + 8 * nt + 2 * t);
            #pragma unroll
            for (int mt = 0; mt < 2; mt++) {
                acc[mt * 8 + nt][0] = bb.x; acc[mt * 8 + nt][1] = bb.y;
                acc[mt * 8 + nt][2] = bb.x; acc[mt * 8 + nt][3] = bb.y;
            }
        }
        #pragma unroll
        for (int kt = 0; kt < 4; kt++) {
            uint32_t ah[2][4], al[2][4];
            #pragma unroll
            for (int mt = 0; mt < 2; mt++) {
                int rb = (16 * mt + g) * 36 + 8 * kt + t;
                ah[mt][0] = Ah[rb];     ah[mt][1] = Ah[rb + 8 * 36];
                ah[mt][2] = Ah[rb + 4]; ah[mt][3] = Ah[rb + 8 * 36 + 4];
                al[mt][0] = Al[rb];     al[mt][1] = Al[rb + 8 * 36];
                al[mt][2] = Al[rb + 4]; al[mt][3] = Al[rb + 8 * 36 + 4];
            }
            #pragma unroll
            for (int nt = 0; nt < 8; nt++) {
                int bi = (8 * nt + g) * 36 + 8 * kt + t;
                uint32_t bh0 = smw[B_W2HI + bi], bh1 = smw[B_W2HI + bi + 4];
                uint32_t bl0 = smw[B_W2LO + bi], bl1 = smw[B_W2LO + bi + 4];
                #pragma unroll
                for (int mt = 0; mt < 2; mt++) {
                    mma16816(acc[mt * 8 + nt], ah[mt], bh0, bh1);
                    mma16816(acc[mt * 8 + nt], ah[mt], bl0, bl1);
                    mma16816(acc[mt * 8 + nt], al[mt], bh0, bh1);
                }
            }
        }

        // ---- m = silu(D); paired red.v4 agg scatter; to matmul2 A frags ----
        uint32_t mh[2][4][4], ml[2][4][4];
        int dtop[2], dbot[2];
        #pragma unroll
        for (int mt = 0; mt < 2; mt++) {
            dtop[mt] = __shfl_sync(0xffffffffu, d, 16 * mt + g);
            dbot[mt] = __shfl_sync(0xffffffffu, d, 16 * mt + g + 8);
        }
        const int colbase_off = 2 * (t & ~1);    // 0,0,4,4
        #pragma unroll
        for (int mt = 0; mt < 2; mt++) {
            #pragma unroll
            for (int nt = 0; nt < 8; nt++) {
                float v0 = silu(acc[mt * 8 + nt][0]);
                float v1 = silu(acc[mt * 8 + nt][1]);
                float v2 = silu(acc[mt * 8 + nt][2]);
                float v3 = silu(acc[mt * 8 + nt][3]);
                if (do_agg) {
                    // pair (t, t^1): even t reds top row quad, odd t reds bottom row quad
                    float px = (t & 1) ? v0 : v2;
                    float qx = (t & 1) ? v1 : v3;
                    float pr = __shfl_xor_sync(0xffffffffu, px, 1);
                    float qr = __shfl_xor_sync(0xffffffffu, qx, 1);
                    int row = (t & 1) ? dbot[mt] : dtop[mt];
                    int col = 8 * nt + colbase_off;
                    float a0 = (t & 1) ? pr : v0;
                    float a1 = (t & 1) ? qr : v1;
                    float a2 = (t & 1) ? v2 : pr;
                    float a3 = (t & 1) ? v3 : qr;
                    red_add_v4(&g_agg[(size_t)row * 64 + col], a0, a1, a2, a3);
                }
                int kt = nt >> 1, o = (nt & 1) * 2;
                bf16_split2(v0, v1, mh[mt][kt][o], ml[mt][kt][o]);
                bf16_split2(v2, v3, mh[mt][kt][o + 1], ml[mt][kt][o + 1]);
            }
        }

        // ---- matmul2: D2 = m @ C1 + cb1 ----
        float acc2[16][4];
        #pragma unroll
        for (int nt = 0; nt < 8; nt++) {
            float2 bb = *(const float2*)(smf + SC_CB1 + 8 * nt + 2 * t);
            #pragma unroll
            for (int mt = 0; mt < 2; mt++) {
                acc2[mt * 8 + nt][0] = bb.x; acc2[mt * 8 + nt][1] = bb.y;
                acc2[mt * 8 + nt][2] = bb.x; acc2[mt * 8 + nt][3] = bb.y;
            }
        }
        #pragma unroll
        for (int kt = 0; kt < 4; kt++) {
            #pragma unroll
            for (int nt = 0; nt < 8; nt++) {
                int bi = (8 * nt + g) * 36 + 8 * kt + t;
                uint32_t bh0 = smw[B_C1HI + bi], bh1 = smw[B_C1HI + bi + 4];
                uint32_t bl0 = smw[B_C1LO + bi], bl1 = smw[B_C1LO + bi + 4];
                #pragma unroll
                for (int mt = 0; mt < 2; mt++) {
                    mma16816(acc2[mt * 8 + nt], mh[mt][kt], bh0, bh1);
                    mma16816(acc2[mt * 8 + nt], mh[mt][kt], bl0, bl1);
                    mma16816(acc2[mt * 8 + nt], ml[mt][kt], bh0, bh1);
                }
            }
        }

        // ---- coord epilogue ----
        float pr0 = 0.f, pr1 = 0.f, pr2 = 0.f, pr3 = 0.f;
        #pragma unroll
        for (int nt = 0; nt < 8; nt++) {
            float2 cwv = *(const float2*)(smf + SC_CW2 + 8 * nt + 2 * t);
            pr0 = fmaf(silu(acc2[nt][0]), cwv.x, pr0);
            pr0 = fmaf(silu(acc2[nt][1]), cwv.y, pr0);
            pr1 = fmaf(silu(acc2[nt][2]), cwv.x, pr1);
            pr1 = fmaf(silu(acc2[nt][3]), cwv.y, pr1);
            pr2 = fmaf(silu(acc2[8 + nt][0]), cwv.x, pr2);
            pr2 = fmaf(silu(acc2[8 + nt][1]), cwv.y, pr2);
            pr3 = fmaf(silu(acc2[8 + nt][2]), cwv.x, pr3);
            pr3 = fmaf(silu(acc2[8 + nt][3]), cwv.y, pr3);
        }
        pr0 += __shfl_xor_sync(0xffffffffu, pr0, 1);
        pr0 += __shfl_xor_sync(0xffffffffu, pr0, 2);
        pr1 += __shfl_xor_sync(0xffffffffu, pr1, 1);
        pr1 += __shfl_xor_sync(0xffffffffu, pr1, 2);
        pr2 += __shfl_xor_sync(0xffffffffu, pr2, 1);
        pr2 += __shfl_xor_sync(0xffffffffu, pr2, 2);
        pr3 += __shfl_xor_sync(0xffffffffu, pr3, 1);
        pr3 += __shfl_xor_sync(0xffffffffu, pr3, 2);
        // lane (g,t) finalizes edge e2 = g + 8*t
        float p = (t == 0) ? pr0 : (t == 1) ? pr1 : (t == 2) ? pr2 : pr3;
        const int e2l = g + 8 * t;
        p += cb2s;
        int dd = __shfl_sync(0xffffffffu, d, e2l);
        float ddx0 = __shfl_sync(0xffffffffu, dx0, e2l);
        float ddx1 = __shfl_sync(0xffffffffu, dx1, e2l);
        float ddx2 = __shfl_sync(0xffffffffu, dx2, e2l);
        atomicAdd(&xn[dd * 3 + 0], ddx0 * p);
        atomicAdd(&xn[dd * 3 + 1], ddx1 * p);
        atomicAdd(&xn[dd * 3 + 2], ddx2 * p);
    }
}

// ---------- node kernel (SIMT) ----------
#define ND_W1   0
#define ND_W2   8192
#define ND_B1   12288
#define ND_B2   12352
#define ND_WARP 12416
#define ND_PW   (32 * 65)
#define ND_SMEMF (ND_WARP + 16 * ND_PW)
#define NSMEM_BYTES (ND_SMEMF * 4)

__global__ void __launch_bounds__(512, 1)
node_kernel(const float* __restrict__ nw1, const float* __restrict__ nb1g,
            const float* __restrict__ nw2, const float* __restrict__ nb2g) {
    extern __shared__ float sm[];
    const int tid = threadIdx.x;
    stage_quad(sm + ND_W1, nw1, 128, tid, 512);
    stage_quad(sm + ND_W2, nw2, 64, tid, 512);
    if (tid < 32) {
        sm[ND_B1 + 2 * tid] = nb1g[tid]; sm[ND_B1 + 2 * tid + 1] = nb1g[tid + 32];
        sm[ND_B2 + 2 * tid] = nb2g[tid]; sm[ND_B2 + 2 * tid + 1] = nb2g[tid + 32];
    }
    __syncthreads();

    const int lane = tid & 31, wrp = tid >> 5;
    float* fb = sm + ND_WARP + wrp * ND_PW;
    float* frow = fb + lane * 65;
    const ulonglong2* W1v = (const ulonglong2*)(sm + ND_W1);
    const ulonglong2* W2v = (const ulonglong2*)(sm + ND_W2);
    const ull* B1 = (const ull*)(sm + ND_B1);
    const ull* B2 = (const ull*)(sm + ND_B2);

    int gw = (blockIdx.x * 512 + tid) >> 5;
    int nwrp = (gridDim.x * 512) >> 5;
    for (int g = gw; g < NODE_GROUPS; g += nwrp) {
        const int base = g * 32;
        ull acc[16];
        float mlo[16], mhi[16];
        #pragma unroll
        for (int a = 0; a < 16; a++) acc[a] = B1[a];
        __syncwarp();
        #pragma unroll 4
        for (int e2 = 0; e2 < 32; e2++) {
            float2 hv = *(const float2*)(g_h + (size_t)(base + e2) * 64 + 2 * lane);
            fb[e2 * 65 + 2 * lane] = hv.x; fb[e2 * 65 + 2 * lane + 1] = hv.y;
        }
        __syncwarp();
        mm_pass16(frow, W1v, acc);
        __syncwarp();
        #pragma unroll 4
        for (int e2 = 0; e2 < 32; e2++) {
            float2 av = *(const float2*)(g_agg + (size_t)(base + e2) * 64 + 2 * lane);
            fb[e2 * 65 + 2 * lane] = av.x; fb[e2 * 65 + 2 * lane + 1] = av.y;
        }
        __syncwarp();
        mm_pass16(frow, W1v + 64 * 16, acc);
        #pragma unroll
        for (int a = 0; a < 16; a++) {
            float2 v = unpack2(acc[a]);
            mlo[a] = silu(v.x); mhi[a] = silu(v.y);
        }
        #pragma unroll
        for (int a = 0; a < 16; a++) acc[a] = B1[16 + a];
        __syncwarp();
        #pragma unroll 4
        for (int e2 = 0; e2 < 32; e2++) {
            float2 hv = *(const float2*)(g_h + (size_t)(base + e2) * 64 + 2 * lane);
            fb[e2 * 65 + 2 * lane] = hv.x; fb[e2 * 65 + 2 * lane + 1] = hv.y;
        }
        __syncwarp();
        mm_pass16(frow, W1v + 8, acc);
        __syncwarp();
        #pragma unroll 4
        for (int e2 = 0; e2 < 32; e2++) {
            float2 av = *(const float2*)(g_agg + (size_t)(base + e2) * 64 + 2 * lane);
            fb[e2 * 65 + 2 * lane] = av.x; fb[e2 * 65 + 2 * lane + 1] = av.y;
        }
        __syncwarp();
        mm_pass16(frow, W1v + 64 * 16 + 8, acc);
        #pragma unroll
        for (int a = 0; a < 16; a++) {
            float2 v = unpack2(acc[a]);
            frow[16 + a] = silu(v.x); frow[48 + a] = silu(v.y);
        }
        #pragma unroll
        for (int a = 0; a < 16; a++) { frow[a] = mlo[a]; frow[32 + a] = mhi[a]; }

        float* hrow = g_h + (size_t)(base + lane) * 64;
        float* arow = g_agg + (size_t)(base + lane) * 64;
        #pragma unroll
        for (int pass = 0; pass < 2; pass++) {
            #pragma unroll
            for (int a = 0; a < 16; a++) acc[a] = B2[16 * pass + a];
            mm_pass16(frow, W2v + 8 * pass, acc);
            #pragma unroll
            for (int t4 = 0; t4 < 4; t4++) {
                float2 v0 = unpack2(acc[4 * t4 + 0]);
                float2 v1 = unpack2(acc[4 * t4 + 1]);
                float2 v2 = unpack2(acc[4 * t4 + 2]);
                float2 v3 = unpack2(acc[4 * t4 + 3]);
                float4 ho = *(const float4*)(hrow + 16 * pass + 4 * t4);
                ho.x += v0.x; ho.y += v1.x; ho.z += v2.x; ho.w += v3.x;
                *(float4*)(hrow + 16 * pass + 4 * t4) = ho;
                float4 hh = *(const float4*)(hrow + 16 * pass + 32 + 4 * t4);
                hh.x += v0.y; hh.y += v1.y; hh.z += v2.y; hh.w += v3.y;
                *(float4*)(hrow + 16 * pass + 32 + 4 * t4) = hh;
                *(float4*)(arow + 16 * pass + 4 * t4) = make_float4(0.f, 0.f, 0.f, 0.f);
                *(float4*)(arow + 16 * pass + 32 + 4 * t4) = make_float4(0.f, 0.f, 0.f, 0.f);
            }
        }
    }
}

// ---------- launch ----------
extern "C" void kernel_launch(void* const* d_in, const int* in_sizes, int n_in,
                              void* d_out, int out_size) {
    const float* x   = (const float*)d_in[0];
    const int*   z   = (const int*)d_in[1];
    const float* t   = (const float*)d_in[2];
    const int*   ei  = (const int*)d_in[3];
    const float* emb = (const float*)d_in[4];
    const float* tw1 = (const float*)d_in[5];
    const float* tb1 = (const float*)d_in[6];
    const float* tw2 = (const float*)d_in[7];
    const float* tb2 = (const float*)d_in[8];
    const float* ew1 = (const float*)d_in[9];
    const float* eb1 = (const float*)d_in[10];
    const float* ew2 = (const float*)d_in[11];
    const float* eb2 = (const float*)d_in[12];
    const float* cw1 = (const float*)d_in[13];
    const float* cb1 = (const float*)d_in[14];
    const float* cw2 = (const float*)d_in[15];
    const float* cb2 = (const float*)d_in[16];
    const float* nw1 = (const float*)d_in[17];
    const float* nb1 = (const float*)d_in[18];
    const float* nw2 = (const float*)d_in[19];
    const float* nb2 = (const float*)d_in[20];
    float* out = (float*)d_out;
    const int B = in_sizes[2];

    float *pxA, *pxB;
    cudaGetSymbolAddress((void**)&pxA, g_xA);
    cudaGetSymbolAddress((void**)&pxB, g_xB);

    cudaFuncSetAttribute(edge_kernel, cudaFuncAttributeMaxDynamicSharedMemorySize, EDGE_SMEM_BYTES);
    cudaFuncSetAttribute(node_kernel, cudaFuncAttributeMaxDynamicSharedMemorySize, NSMEM_BYTES);
    cudaFuncSetAttribute(pre_kernel,  cudaFuncAttributeMaxDynamicSharedMemorySize, P_SMEM_BYTES);

    const size_t XB = (size_t)N_NODES * 3 * sizeof(float);
    const int EGRID = 304;   // 2 CTAs/SM x 152
    const int PGRID = 304;

    init_kernel<<<(N_NODES * HID + 255) / 256, 256>>>(z, emb, t, tw1, tb1, tw2, tb2, B);

    // ---- layer 0 ----
    pre_kernel<<<PGRID, 192, P_SMEM_BYTES>>>(ew1 + 0 * 129 * 64, eb1 + 0 * 64);
    cudaMemcpyAsync(pxB, x, XB, cudaMemcpyDeviceToDevice, 0);
    edge_kernel<<<EGRID, 128, EDGE_SMEM_BYTES>>>(x, pxB, ei,
        ew1 + 0 * 129 * 64 + 128 * 64, ew2 + 0 * 4096, eb2 + 0 * 64,
        cw1 + 0 * 4096, cb1 + 0 * 64, cw2 + 0 * 64, cb2 + 0, 1);
    node_kernel<<<152, 512, NSMEM_BYTES>>>(nw1 + 0 * 128 * 64, nb1 + 0 * 64,
                                           nw2 + 0 * 4096, nb2 + 0 * 64);

    // ---- layer 1 ----
    pre_kernel<<<PGRID, 192, P_SMEM_BYTES>>>(ew1 + 1 * 129 * 64, eb1 + 1 * 64);
    cudaMemcpyAsync(pxA, pxB, XB, cudaMemcpyDeviceToDevice, 0);
    edge_kernel<<<EGRID, 128, EDGE_SMEM_BYTES>>>(pxB, pxA, ei,
        ew1 + 1 * 129 * 64 + 128 * 64, ew2 + 1 * 4096, eb2 + 1 * 64,
        cw1 + 1 * 4096, cb1 + 1 * 64, cw2 + 1 * 64, cb2 + 1, 1);
    node_kernel<<<152, 512, NSMEM_BYTES>>>(nw1 + 1 * 128 * 64, nb1 + 1 * 64,
                                           nw2 + 1 * 4096, nb2 + 1 * 64);

    // ---- layer 2: agg/node dead, write x' straight to d_out ----
    pre_kernel<<<PGRID, 192, P_SMEM_BYTES>>>(ew1 + 2 * 129 * 64, eb1 + 2 * 64);
    cudaMemcpyAsync(out, pxA, XB, cudaMemcpyDeviceToDevice, 0);
    edge_kernel<<<EGRID, 128, EDGE_SMEM_BYTES>>>(pxA, out, ei,
        ew1 + 2 * 129 * 64 + 128 * 64, ew2 + 2 * 4096, eb2 + 2 * 64,
        cw1 + 2 * 4096, cb1 + 2 * 64, cw2 + 2 * 64, cb2 + 2, 0);
}

// round 9
// speedup vs baseline: 1.7720x; 1.0955x over previous
#include <cuda_runtime.h>
#include <cuda_bf16.h>
#include <cstdint>

#define N_NODES 100000
#define N_EDGES 1600000
#define HID 64
#define NGROUPS (N_EDGES / 32)       // 50000
#define NODE_GROUPS (N_NODES / 32)   // 3125

typedef unsigned long long ull;

// ---------- device scratch ----------
__device__ float g_h[N_NODES * HID];
__device__ float g_agg[N_NODES * HID];
__device__ float g_P[N_NODES * HID];
__device__ float g_Q[N_NODES * HID];
__device__ float g_xA[N_NODES * 3];
__device__ float g_xB[N_NODES * 3];

// ---------- helpers ----------
__device__ __forceinline__ float silu(float v) {
    float u = 0.5f * v, th;
    asm("tanh.approx.f32 %0, %1;" : "=f"(th) : "f"(u));
    return v * fmaf(th, 0.5f, 0.5f);
}
__device__ __forceinline__ void red_add_v4(float* addr, float a, float b, float c, float d) {
    asm volatile("red.global.add.v4.f32 [%0], {%1, %2, %3, %4};"
                 :: "l"(addr), "f"(a), "f"(b), "f"(c), "f"(d) : "memory");
}
__device__ __forceinline__ void bf16_split2(float f0, float f1, uint32_t& hi, uint32_t& lo) {
    uint32_t h;
    asm("cvt.rn.bf16x2.f32 %0, %1, %2;" : "=r"(h) : "f"(f1), "f"(f0));
    float h0 = __uint_as_float(h << 16);
    float h1 = __uint_as_float(h & 0xffff0000u);
    float l0 = f0 - h0, l1 = f1 - h1;
    uint32_t l;
    asm("cvt.rn.bf16x2.f32 %0, %1, %2;" : "=r"(l) : "f"(l1), "f"(l0));
    hi = h; lo = l;
}
__device__ __forceinline__ void mma16816(float c[4], const uint32_t a[4],
                                         uint32_t b0, uint32_t b1) {
    asm volatile(
        "mma.sync.aligned.m16n8k16.row.col.f32.bf16.bf16.f32 "
        "{%0,%1,%2,%3}, {%4,%5,%6,%7}, {%8,%9}, {%0,%1,%2,%3};"
        : "+f"(c[0]), "+f"(c[1]), "+f"(c[2]), "+f"(c[3])
        : "r"(a[0]), "r"(a[1]), "r"(a[2]), "r"(a[3]), "r"(b0), "r"(b1));
}
// stage a 64x64 fp32 weight (row-major [k][n]) as bf16 hi/lo B-tiles [n][kk], stride 36
__device__ __forceinline__ void stage_btile(uint32_t* dhi, uint32_t* dlo,
                                            const float* __restrict__ W, int tid, int nth) {
    for (int i = tid; i < 2048; i += nth) {
        int n = i >> 5, kk = i & 31;
        uint32_t hi, lo;
        bf16_split2(W[(2 * kk) * 64 + n], W[(2 * kk + 1) * 64 + n], hi, lo);
        dhi[n * 36 + kk] = hi;
        dlo[n * 36 + kk] = lo;
    }
}
// 3-term (Ahi*Bhi + Ahi*Blo + Alo*Bhi) K=64 mma, A from smem
__device__ __forceinline__ void mma3_smem(float acc[16][4],
                                          const uint32_t* __restrict__ Ah,
                                          const uint32_t* __restrict__ Al,
                                          const uint32_t* __restrict__ Bh,
                                          const uint32_t* __restrict__ Bl,
                                          int g, int t) {
    #pragma unroll
    for (int kt = 0; kt < 4; kt++) {
        uint32_t ah[2][4], al[2][4];
        #pragma unroll
        for (int mt = 0; mt < 2; mt++) {
            int rb = (16 * mt + g) * 36 + 8 * kt + t;
            ah[mt][0] = Ah[rb];     ah[mt][1] = Ah[rb + 8 * 36];
            ah[mt][2] = Ah[rb + 4]; ah[mt][3] = Ah[rb + 8 * 36 + 4];
            al[mt][0] = Al[rb];     al[mt][1] = Al[rb + 8 * 36];
            al[mt][2] = Al[rb + 4]; al[mt][3] = Al[rb + 8 * 36 + 4];
        }
        #pragma unroll
        for (int nt = 0; nt < 8; nt++) {
            int bi = (8 * nt + g) * 36 + 8 * kt + t;
            uint32_t bh0 = Bh[bi], bh1 = Bh[bi + 4];
            uint32_t bl0 = Bl[bi], bl1 = Bl[bi + 4];
            #pragma unroll
            for (int mt = 0; mt < 2; mt++) {
                mma16816(acc[mt * 8 + nt], ah[mt], bh0, bh1);
                mma16816(acc[mt * 8 + nt], ah[mt], bl0, bl1);
                mma16816(acc[mt * 8 + nt], al[mt], bh0, bh1);
            }
        }
    }
}
// 3-term K=64 mma, A from register fragments
__device__ __forceinline__ void mma3_reg(float acc[16][4],
                                         const uint32_t fh[2][4][4],
                                         const uint32_t fl[2][4][4],
                                         const uint32_t* __restrict__ Bh,
                                         const uint32_t* __restrict__ Bl,
                                         int g, int t) {
    #pragma unroll
    for (int kt = 0; kt < 4; kt++) {
        #pragma unroll
        for (int nt = 0; nt < 8; nt++) {
            int bi = (8 * nt + g) * 36 + 8 * kt + t;
            uint32_t bh0 = Bh[bi], bh1 = Bh[bi + 4];
            uint32_t bl0 = Bl[bi], bl1 = Bl[bi + 4];
            #pragma unroll
            for (int mt = 0; mt < 2; mt++) {
                mma16816(acc[mt * 8 + nt], fh[mt][kt], bh0, bh1);
                mma16816(acc[mt * 8 + nt], fh[mt][kt], bl0, bl1);
                mma16816(acc[mt * 8 + nt], fl[mt][kt], bh0, bh1);
            }
        }
    }
}

// ---------- init ----------
__global__ void init_kernel(const int* __restrict__ z, const float* __restrict__ emb,
                            const float* __restrict__ t,
                            const float* __restrict__ tw1, const float* __restrict__ tb1,
                            const float* __restrict__ tw2, const float* __restrict__ tb2,
                            int B) {
    __shared__ float s1[HID];
    __shared__ float tm[HID];
    int tidb = threadIdx.x;
    if (tidb < HID) {
        float w = tw1[tidb], bb = tb1[tidb];
        float acc = 0.f;
        for (int b = 0; b < B; b++) acc += silu(t[b] * w + bb);
        s1[tidb] = acc / (float)B;
    }
    __syncthreads();
    if (tidb < HID) {
        float o = tb2[tidb];
        for (int k = 0; k < HID; k++) o += s1[k] * tw2[k * HID + tidb];
        tm[tidb] = o;
    }
    __syncthreads();
    int i = blockIdx.x * blockDim.x + tidb;
    if (i < N_NODES * HID) {
        int node = i >> 6, j = i & 63;
        g_h[i] = emb[z[node] * HID + j] + tm[j];
        g_agg[i] = 0.f;
    }
}

// ---------- pre kernel (layer 0 only): P = h@W1a + b1, Q = h@W1b ----------
#define PW_AH 0
#define PW_AL 2304
#define PW_BH 4608
#define PW_BL 6912
#define P_B1W 9216
#define P_WBASE 9280
#define P_WW 2304
#define P_SMEM_WORDS (P_WBASE + 6 * P_WW)
#define P_SMEM_BYTES (P_SMEM_WORDS * 4)

__global__ void __launch_bounds__(192)
pre_kernel(const float* __restrict__ ew1, const float* __restrict__ eb1g) {
    extern __shared__ uint32_t smw[];
    float* smf = (float*)smw;
    const int tid = threadIdx.x;

    stage_btile(smw + PW_AH, smw + PW_AL, ew1, tid, 192);
    stage_btile(smw + PW_BH, smw + PW_BL, ew1 + 64 * 64, tid, 192);
    if (tid < 64) smf[P_B1W + tid] = eb1g[tid];
    __syncthreads();

    const int lane = tid & 31;
    const int wrp = tid >> 5;
    const int g = lane >> 2;
    const int t = lane & 3;
    uint32_t* Ah = smw + P_WBASE + wrp * P_WW;
    uint32_t* Al = Ah + 1152;

    const int gwarp = (blockIdx.x * 192 + tid) >> 5;
    const int nwarps = (gridDim.x * 192) >> 5;

    for (int grp = gwarp; grp < NODE_GROUPS; grp += nwarps) {
        const int base = grp * 32;
        __syncwarp();
        #pragma unroll 4
        for (int e2 = 0; e2 < 32; e2++) {
            float2 hv = __ldg((const float2*)(g_h + (size_t)(base + e2) * 64 + 2 * lane));
            uint32_t hi, lo;
            bf16_split2(hv.x, hv.y, hi, lo);
            Ah[e2 * 36 + lane] = hi;
            Al[e2 * 36 + lane] = lo;
        }
        __syncwarp();

        float accP[16][4], accQ[16][4];
        #pragma unroll
        for (int nt = 0; nt < 8; nt++) {
            float2 bb = *(const float2*)(smf + P_B1W + 8 * nt + 2 * t);
            #pragma unroll
            for (int mt = 0; mt < 2; mt++) {
                accP[mt * 8 + nt][0] = bb.x; accP[mt * 8 + nt][1] = bb.y;
                accP[mt * 8 + nt][2] = bb.x; accP[mt * 8 + nt][3] = bb.y;
                accQ[mt * 8 + nt][0] = 0.f; accQ[mt * 8 + nt][1] = 0.f;
                accQ[mt * 8 + nt][2] = 0.f; accQ[mt * 8 + nt][3] = 0.f;
            }
        }
        mma3_smem(accP, Ah, Al, smw + PW_AH, smw + PW_AL, g, t);
        mma3_smem(accQ, Ah, Al, smw + PW_BH, smw + PW_BL, g, t);
        #pragma unroll
        for (int mt = 0; mt < 2; mt++) {
            int r1 = base + 16 * mt + g;
            int r2 = r1 + 8;
            #pragma unroll
            for (int nt = 0; nt < 8; nt++) {
                int c = 8 * nt + 2 * t;
                *(float2*)(g_P + (size_t)r1 * 64 + c) = make_float2(accP[mt * 8 + nt][0], accP[mt * 8 + nt][1]);
                *(float2*)(g_P + (size_t)r2 * 64 + c) = make_float2(accP[mt * 8 + nt][2], accP[mt * 8 + nt][3]);
                *(float2*)(g_Q + (size_t)r1 * 64 + c) = make_float2(accQ[mt * 8 + nt][0], accQ[mt * 8 + nt][1]);
                *(float2*)(g_Q + (size_t)r2 * 64 + c) = make_float2(accQ[mt * 8 + nt][2], accQ[mt * 8 + nt][3]);
            }
        }
    }
}

// ---------- edge kernel (round-8, unchanged) ----------
#define B_W2HI 0
#define B_W2LO 2304
#define B_C1HI 4608
#define B_C1LO 6912
#define SC_W1C 9216
#define SC_B2  9280
#define SC_CB1 9344
#define SC_CW2 9408
#define SC_CB2 9472
#define WARP_BASE 9480
#define WARP_W 2304
#define EDGE_SMEM_WORDS (WARP_BASE + 4 * WARP_W)
#define EDGE_SMEM_BYTES (EDGE_SMEM_WORDS * 4)

__global__ void __launch_bounds__(128)
edge_kernel(const float* __restrict__ x, float* __restrict__ xn,
            const int* __restrict__ ei,
            const float* __restrict__ w1c_g,
            const float* __restrict__ ew2, const float* __restrict__ eb2g,
            const float* __restrict__ cw1, const float* __restrict__ cb1g,
            const float* __restrict__ cw2g, const float* __restrict__ cb2g,
            int do_agg) {
    extern __shared__ uint32_t smw[];
    float* smf = (float*)smw;
    const int tid = threadIdx.x;

    stage_btile(smw + B_W2HI, smw + B_W2LO, ew2, tid, 128);
    stage_btile(smw + B_C1HI, smw + B_C1LO, cw1, tid, 128);
    if (tid < 64) {
        smf[SC_W1C + tid] = w1c_g[tid];
        smf[SC_B2 + tid]  = eb2g[tid];
        smf[SC_CB1 + tid] = cb1g[tid];
        smf[SC_CW2 + tid] = cw2g[tid];
    }
    if (tid == 0) smf[SC_CB2] = cb2g[0];
    __syncthreads();

    const int lane = tid & 31;
    const int wrp = tid >> 5;
    const int g = lane >> 2;
    const int t = lane & 3;
    uint32_t* Ah = smw + WARP_BASE + wrp * WARP_W;
    uint32_t* Al = Ah + 1152;
    const float w1c0 = smf[SC_W1C + 2 * lane];
    const float w1c1 = smf[SC_W1C + 2 * lane + 1];
    const float cb2s = smf[SC_CB2];

    const int gwarp = (blockIdx.x * 128 + tid) >> 5;
    const int nwarps = (gridDim.x * 128) >> 5;

    int grp = gwarp;
    int s_n = 0, d_n = 0;
    float xs0 = 0, xs1 = 0, xs2 = 0, xd0 = 0, xd1 = 0, xd2 = 0;
    if (grp < NGROUPS) {
        int e = grp * 32 + lane;
        s_n = ei[e]; d_n = ei[N_EDGES + e];
        xs0 = __ldg(&x[s_n * 3 + 0]); xs1 = __ldg(&x[s_n * 3 + 1]); xs2 = __ldg(&x[s_n * 3 + 2]);
        xd0 = __ldg(&x[d_n * 3 + 0]); xd1 = __ldg(&x[d_n * 3 + 1]); xd2 = __ldg(&x[d_n * 3 + 2]);
    }

    for (; grp < NGROUPS; grp += nwarps) {
        const int s = s_n, d = d_n;
        const float dx0 = xd0 - xs0;
        const float dx1 = xd1 - xs1;
        const float dx2 = xd2 - xs2;
        const float r2 = dx0 * dx0 + dx1 * dx1 + dx2 * dx2;

        __syncwarp();
        #pragma unroll 4
        for (int e2 = 0; e2 < 32; e2++) {
            int nd = __shfl_sync(0xffffffffu, d, e2);
            int ns = __shfl_sync(0xffffffffu, s, e2);
            float rr = __shfl_sync(0xffffffffu, r2, e2);
            float2 pv = __ldg((const float2*)(g_P + (size_t)nd * 64 + 2 * lane));
            float2 qv = __ldg((const float2*)(g_Q + (size_t)ns * 64 + 2 * lane));
            float f0 = silu(fmaf(rr, w1c0, pv.x + qv.x));
            float f1 = silu(fmaf(rr, w1c1, pv.y + qv.y));
            uint32_t hi, lo;
            bf16_split2(f0, f1, hi, lo);
            Ah[e2 * 36 + lane] = hi;
            Al[e2 * 36 + lane] = lo;
        }
        __syncwarp();

        {
            int gn = grp + nwarps;
            if (gn < NGROUPS) {
                int e = gn * 32 + lane;
                s_n = ei[e]; d_n = ei[N_EDGES + e];
                xs0 = __ldg(&x[s_n * 3 + 0]); xs1 = __ldg(&x[s_n * 3 + 1]); xs2 = __ldg(&x[s_n * 3 + 2]);
                xd0 = __ldg(&x[d_n * 3 + 0]); xd1 = __ldg(&x[d_n * 3 + 1]); xd2 = __ldg(&x[d_n * 3 + 2]);
            }
        }

        // ---- matmul1: D = ef1 @ W2 + b2 ----
        float acc[16][4];
        #pragma unroll
        for (int nt = 0; nt < 8; nt++) {
            float2 bb = *(const float2*)(smf + SC_B2 + 8 * nt + 2 * t);
            #pragma unroll
            for (int mt = 0; mt < 2; mt++) {
                acc[mt * 8 + nt][0] = bb.x; acc[mt * 8 + nt][1] = bb.y;
                acc[mt * 8 + nt][2] = bb.x; acc[mt * 8 + nt][3] = bb.y;
            }
        }
        mma3_smem(acc, Ah, Al, smw + B_W2HI, smw + B_W2LO, g, t);

        // ---- m = silu(D); paired red.v4; to matmul2 A frags ----
        uint32_t mh[2][4][4], ml[2][4][4];
        int dtop[2], dbot[2];
        #pragma unroll
        for (int mt = 0; mt < 2; mt++) {
            dtop[mt] = __shfl_sync(0xffffffffu, d, 16 * mt + g);
            dbot[mt] = __shfl_sync(0xffffffffu, d, 16 * mt + g + 8);
        }
        const int colbase_off = 2 * (t & ~1);
        #pragma unroll
        for (int mt = 0; mt < 2; mt++) {
            #pragma unroll
            for (int nt = 0; nt < 8; nt++) {
                float v0 = silu(acc[mt * 8 + nt][0]);
                float v1 = silu(acc[mt * 8 + nt][1]);
                float v2 = silu(acc[mt * 8 + nt][2]);
                float v3 = silu(acc[mt * 8 + nt][3]);
                if (do_agg) {
                    float px = (t & 1) ? v0 : v2;
                    float qx = (t & 1) ? v1 : v3;
                    float pr = __shfl_xor_sync(0xffffffffu, px, 1);
                    float qr = __shfl_xor_sync(0xffffffffu, qx, 1);
                    int row = (t & 1) ? dbot[mt] : dtop[mt];
                    int col = 8 * nt + colbase_off;
                    float a0 = (t & 1) ? pr : v0;
                    float a1 = (t & 1) ? qr : v1;
                    float a2 = (t & 1) ? v2 : pr;
                    float a3 = (t & 1) ? v3 : qr;
                    red_add_v4(&g_agg[(size_t)row * 64 + col], a0, a1, a2, a3);
                }
                int kt = nt >> 1, o = (nt & 1) * 2;
                bf16_split2(v0, v1, mh[mt][kt][o], ml[mt][kt][o]);
                bf16_split2(v2, v3, mh[mt][kt][o + 1], ml[mt][kt][o + 1]);
            }
        }

        // ---- matmul2: D2 = m @ C1 + cb1 ----
        float acc2[16][4];
        #pragma unroll
        for (int nt = 0; nt < 8; nt++) {
            float2 bb = *(const float2*)(smf + SC_CB1 + 8 * nt + 2 * t);
            #pragma unroll
            for (int mt = 0; mt < 2; mt++) {
                acc2[mt * 8 + nt][0] = bb.x; acc2[mt * 8 + nt][1] = bb.y;
                acc2[mt * 8 + nt][2] = bb.x; acc2[mt * 8 + nt][3] = bb.y;
            }
        }
        mma3_reg(acc2, mh, ml, smw + B_C1HI, smw + B_C1LO, g, t);

        // ---- coord epilogue ----
        float pr0 = 0.f, pr1 = 0.f, pr2 = 0.f, pr3 = 0.f;
        #pragma unroll
        for (int nt = 0; nt < 8; nt++) {
            float2 cwv = *(const float2*)(smf + SC_CW2 + 8 * nt + 2 * t);
            pr0 = fmaf(silu(acc2[nt][0]), cwv.x, pr0);
            pr0 = fmaf(silu(acc2[nt][1]), cwv.y, pr0);
            pr1 = fmaf(silu(acc2[nt][2]), cwv.x, pr1);
            pr1 = fmaf(silu(acc2[nt][3]), cwv.y, pr1);
            pr2 = fmaf(silu(acc2[8 + nt][0]), cwv.x, pr2);
            pr2 = fmaf(silu(acc2[8 + nt][1]), cwv.y, pr2);
            pr3 = fmaf(silu(acc2[8 + nt][2]), cwv.x, pr3);
            pr3 = fmaf(silu(acc2[8 + nt][3]), cwv.y, pr3);
        }
        pr0 += __shfl_xor_sync(0xffffffffu, pr0, 1);
        pr0 += __shfl_xor_sync(0xffffffffu, pr0, 2);
        pr1 += __shfl_xor_sync(0xffffffffu, pr1, 1);
        pr1 += __shfl_xor_sync(0xffffffffu, pr1, 2);
        pr2 += __shfl_xor_sync(0xffffffffu, pr2, 1);
        pr2 += __shfl_xor_sync(0xffffffffu, pr2, 2);
        pr3 += __shfl_xor_sync(0xffffffffu, pr3, 1);
        pr3 += __shfl_xor_sync(0xffffffffu, pr3, 2);
        float p = (t == 0) ? pr0 : (t == 1) ? pr1 : (t == 2) ? pr2 : pr3;
        const int e2l = g + 8 * t;
        p += cb2s;
        int dd = __shfl_sync(0xffffffffu, d, e2l);
        float ddx0 = __shfl_sync(0xffffffffu, dx0, e2l);
        float ddx1 = __shfl_sync(0xffffffffu, dx1, e2l);
        float ddx2 = __shfl_sync(0xffffffffu, dx2, e2l);
        atomicAdd(&xn[dd * 3 + 0], ddx0 * p);
        atomicAdd(&xn[dd * 3 + 1], ddx1 * p);
        atomicAdd(&xn[dd * 3 + 2], ddx2 * p);
    }
}

// ---------- node kernel (mma.sync) + fused next-layer P/Q ----------
// smem words
#define N_W1HH 0
#define N_W1HL 2304
#define N_W1AH 4608
#define N_W1AL 6912
#define N_W2H  9216
#define N_W2L  11520
#define N_PAH  13824
#define N_PAL  16128
#define N_PBH  18432
#define N_PBL  20736
#define N_B1W  23040
#define N_B2W  23104
#define N_EB1W 23168
#define N_ABASE 23232
#define N_AW   2304
#define NODE_SMEM_WORDS (N_ABASE + 8 * N_AW)
#define NODE_SMEM_BYTES (NODE_SMEM_WORDS * 4)   // 166,656 B -> 1 CTA/SM

__global__ void __launch_bounds__(256)
node_kernel(const float* __restrict__ nw1, const float* __restrict__ nb1g,
            const float* __restrict__ nw2, const float* __restrict__ nb2g,
            const float* __restrict__ ew1n, const float* __restrict__ eb1n) {
    extern __shared__ uint32_t smw[];
    float* smf = (float*)smw;
    const int tid = threadIdx.x;

    stage_btile(smw + N_W1HH, smw + N_W1HL, nw1, tid, 256);            // W1 rows 0-63 (h)
    stage_btile(smw + N_W1AH, smw + N_W1AL, nw1 + 64 * 64, tid, 256);  // W1 rows 64-127 (agg)
    stage_btile(smw + N_W2H, smw + N_W2L, nw2, tid, 256);
    stage_btile(smw + N_PAH, smw + N_PAL, ew1n, tid, 256);             // next-layer W1a
    stage_btile(smw + N_PBH, smw + N_PBL, ew1n + 64 * 64, tid, 256);   // next-layer W1b
    if (tid < 64) {
        smf[N_B1W + tid]  = nb1g[tid];
        smf[N_B2W + tid]  = nb2g[tid];
        smf[N_EB1W + tid] = eb1n[tid];
    }
    __syncthreads();

    const int lane = tid & 31;
    const int wrp = tid >> 5;
    const int g = lane >> 2;
    const int t = lane & 3;
    uint32_t* Ah = smw + N_ABASE + wrp * N_AW;
    uint32_t* Al = Ah + 1152;

    const int gwarp = (blockIdx.x * 256 + tid) >> 5;
    const int nwarps = (gridDim.x * 256) >> 5;

    for (int grp = gwarp; grp < NODE_GROUPS; grp += nwarps) {
        const int base = grp * 32;

        // ---- gather h -> A frags ----
        __syncwarp();
        #pragma unroll 4
        for (int e2 = 0; e2 < 32; e2++) {
            float2 hv = __ldg((const float2*)(g_h + (size_t)(base + e2) * 64 + 2 * lane));
            uint32_t hi, lo;
            bf16_split2(hv.x, hv.y, hi, lo);
            Ah[e2 * 36 + lane] = hi;
            Al[e2 * 36 + lane] = lo;
        }
        __syncwarp();

        // ---- acc1 = [h] @ W1h + b1 ----
        float acc1[16][4];
        #pragma unroll
        for (int nt = 0; nt < 8; nt++) {
            float2 bb = *(const float2*)(smf + N_B1W + 8 * nt + 2 * t);
            #pragma unroll
            for (int mt = 0; mt < 2; mt++) {
                acc1[mt * 8 + nt][0] = bb.x; acc1[mt * 8 + nt][1] = bb.y;
                acc1[mt * 8 + nt][2] = bb.x; acc1[mt * 8 + nt][3] = bb.y;
            }
        }
        mma3_smem(acc1, Ah, Al, smw + N_W1HH, smw + N_W1HL, g, t);

        // ---- gather agg (and zero it) -> A frags; accumulate @ W1agg ----
        __syncwarp();
        #pragma unroll 4
        for (int e2 = 0; e2 < 32; e2++) {
            float2* ap = (float2*)(g_agg + (size_t)(base + e2) * 64 + 2 * lane);
            float2 av = *ap;
            *ap = make_float2(0.f, 0.f);
            uint32_t hi, lo;
            bf16_split2(av.x, av.y, hi, lo);
            Ah[e2 * 36 + lane] = hi;
            Al[e2 * 36 + lane] = lo;
        }
        __syncwarp();
        mma3_smem(acc1, Ah, Al, smw + N_W1AH, smw + N_W1AL, g, t);

        // ---- hid = silu(acc1) -> register A frags ----
        uint32_t mh[2][4][4], ml[2][4][4];
        #pragma unroll
        for (int mt = 0; mt < 2; mt++) {
            #pragma unroll
            for (int nt = 0; nt < 8; nt++) {
                float v0 = silu(acc1[mt * 8 + nt][0]);
                float v1 = silu(acc1[mt * 8 + nt][1]);
                float v2 = silu(acc1[mt * 8 + nt][2]);
                float v3 = silu(acc1[mt * 8 + nt][3]);
                int kt = nt >> 1, o = (nt & 1) * 2;
                bf16_split2(v0, v1, mh[mt][kt][o], ml[mt][kt][o]);
                bf16_split2(v2, v3, mh[mt][kt][o + 1], ml[mt][kt][o + 1]);
            }
        }

        // ---- acc2 = hid @ W2 + b2; h_new = h_old + acc2 ----
        float acc2[16][4];
        #pragma unroll
        for (int nt = 0; nt < 8; nt++) {
            float2 bb = *(const float2*)(smf + N_B2W + 8 * nt + 2 * t);
            #pragma unroll
            for (int mt = 0; mt < 2; mt++) {
                acc2[mt * 8 + nt][0] = bb.x; acc2[mt * 8 + nt][1] = bb.y;
                acc2[mt * 8 + nt][2] = bb.x; acc2[mt * 8 + nt][3] = bb.y;
            }
        }
        mma3_reg(acc2, mh, ml, smw + N_W2H, smw + N_W2L, g, t);

        // residual in fragment layout + writeback + convert to A frags for P/Q
        uint32_t hh[2][4][4], hl[2][4][4];
        #pragma unroll
        for (int mt = 0; mt < 2; mt++) {
            int r1 = base + 16 * mt + g;
            int r2 = r1 + 8;
            #pragma unroll
            for (int nt = 0; nt < 8; nt++) {
                int c = 8 * nt + 2 * t;
                float2 h1 = __ldg((const float2*)(g_h + (size_t)r1 * 64 + c));
                float2 h2 = __ldg((const float2*)(g_h + (size_t)r2 * 64 + c));
                float v0 = h1.x + acc2[mt * 8 + nt][0];
                float v1 = h1.y + acc2[mt * 8 + nt][1];
                float v2 = h2.x + acc2[mt * 8 + nt][2];
                float v3 = h2.y + acc2[mt * 8 + nt][3];
                *(float2*)(g_h + (size_t)r1 * 64 + c) = make_float2(v0, v1);
                *(float2*)(g_h + (size_t)r2 * 64 + c) = make_float2(v2, v3);
                int kt = nt >> 1, o = (nt & 1) * 2;
                bf16_split2(v0, v1, hh[mt][kt][o], hl[mt][kt][o]);
                bf16_split2(v2, v3, hh[mt][kt][o + 1], hl[mt][kt][o + 1]);
            }
        }

        // ---- P = h_new @ W1a' + b1' ----
        float accp[16][4];
        #pragma unroll
        for (int nt = 0; nt < 8; nt++) {
            float2 bb = *(const float2*)(smf + N_EB1W + 8 * nt + 2 * t);
            #pragma unroll
            for (int mt = 0; mt < 2; mt++) {
                accp[mt * 8 + nt][0] = bb.x; accp[mt * 8 + nt][1] = bb.y;
                accp[mt * 8 + nt][2] = bb.x; accp[mt * 8 + nt][3] = bb.y;
            }
        }
        mma3_reg(accp, hh, hl, smw + N_PAH, smw + N_PAL, g, t);
        #pragma unroll
        for (int mt = 0; mt < 2; mt++) {
            int r1 = base + 16 * mt + g;
            int r2 = r1 + 8;
            #pragma unroll
            for (int nt = 0; nt < 8; nt++) {
                int c = 8 * nt + 2 * t;
                *(float2*)(g_P + (size_t)r1 * 64 + c) = make_float2(accp[mt * 8 + nt][0], accp[mt * 8 + nt][1]);
                *(float2*)(g_P + (size_t)r2 * 64 + c) = make_float2(accp[mt * 8 + nt][2], accp[mt * 8 + nt][3]);
            }
        }

        // ---- Q = h_new @ W1b' ----
        #pragma unroll
        for (int a = 0; a < 16; a++) {
            accp[a][0] = 0.f; accp[a][1] = 0.f; accp[a][2] = 0.f; accp[a][3] = 0.f;
        }
        mma3_reg(accp, hh, hl, smw + N_PBH, smw + N_PBL, g, t);
        #pragma unroll
        for (int mt = 0; mt < 2; mt++) {
            int r1 = base + 16 * mt + g;
            int r2 = r1 + 8;
            #pragma unroll
            for (int nt = 0; nt < 8; nt++) {
                int c = 8 * nt + 2 * t;
                *(float2*)(g_Q + (size_t)r1 * 64 + c) = make_float2(accp[mt * 8 + nt][0], accp[mt * 8 + nt][1]);
                *(float2*)(g_Q + (size_t)r2 * 64 + c) = make_float2(accp[mt * 8 + nt][2], accp[mt * 8 + nt][3]);
            }
        }
    }
}

// ---------- launch ----------
extern "C" void kernel_launch(void* const* d_in, const int* in_sizes, int n_in,
                              void* d_out, int out_size) {
    const float* x   = (const float*)d_in[0];
    const int*   z   = (const int*)d_in[1];
    const float* t   = (const float*)d_in[2];
    const int*   ei  = (const int*)d_in[3];
    const float* emb = (const float*)d_in[4];
    const float* tw1 = (const float*)d_in[5];
    const float* tb1 = (const float*)d_in[6];
    const float* tw2 = (const float*)d_in[7];
    const float* tb2 = (const float*)d_in[8];
    const float* ew1 = (const float*)d_in[9];
    const float* eb1 = (const float*)d_in[10];
    const float* ew2 = (const float*)d_in[11];
    const float* eb2 = (const float*)d_in[12];
    const float* cw1 = (const float*)d_in[13];
    const float* cb1 = (const float*)d_in[14];
    const float* cw2 = (const float*)d_in[15];
    const float* cb2 = (const float*)d_in[16];
    const float* nw1 = (const float*)d_in[17];
    const float* nb1 = (const float*)d_in[18];
    const float* nw2 = (const float*)d_in[19];
    const float* nb2 = (const float*)d_in[20];
    float* out = (float*)d_out;
    const int B = in_sizes[2];

    float *pxA, *pxB;
    cudaGetSymbolAddress((void**)&pxA, g_xA);
    cudaGetSymbolAddress((void**)&pxB, g_xB);

    cudaFuncSetAttribute(edge_kernel, cudaFuncAttributeMaxDynamicSharedMemorySize, EDGE_SMEM_BYTES);
    cudaFuncSetAttribute(node_kernel, cudaFuncAttributeMaxDynamicSharedMemorySize, NODE_SMEM_BYTES);
    cudaFuncSetAttribute(pre_kernel,  cudaFuncAttributeMaxDynamicSharedMemorySize, P_SMEM_BYTES);

    const size_t XB = (size_t)N_NODES * 3 * sizeof(float);
    const int EGRID = 304;

    init_kernel<<<(N_NODES * HID + 255) / 256, 256>>>(z, emb, t, tw1, tb1, tw2, tb2, B);

    // ---- layer 0 ----
    pre_kernel<<<304, 192, P_SMEM_BYTES>>>(ew1 + 0 * 129 * 64, eb1 + 0 * 64);
    cudaMemcpyAsync(pxB, x, XB, cudaMemcpyDeviceToDevice, 0);
    edge_kernel<<<EGRID, 128, EDGE_SMEM_BYTES>>>(x, pxB, ei,
        ew1 + 0 * 129 * 64 + 128 * 64, ew2 + 0 * 4096, eb2 + 0 * 64,
        cw1 + 0 * 4096, cb1 + 0 * 64, cw2 + 0 * 64, cb2 + 0, 1);
    // node0: h update + P/Q for layer 1
    node_kernel<<<152, 256, NODE_SMEM_BYTES>>>(nw1 + 0 * 128 * 64, nb1 + 0 * 64,
                                               nw2 + 0 * 4096, nb2 + 0 * 64,
                                               ew1 + 1 * 129 * 64, eb1 + 1 * 64);

    // ---- layer 1 ----
    cudaMemcpyAsync(pxA, pxB, XB, cudaMemcpyDeviceToDevice, 0);
    edge_kernel<<<EGRID, 128, EDGE_SMEM_BYTES>>>(pxB, pxA, ei,
        ew1 + 1 * 129 * 64 + 128 * 64, ew2 + 1 * 4096, eb2 + 1 * 64,
        cw1 + 1 * 4096, cb1 + 1 * 64, cw2 + 1 * 64, cb2 + 1, 1);
    // node1: h update + P/Q for layer 2
    node_kernel<<<152, 256, NODE_SMEM_BYTES>>>(nw1 + 1 * 128 * 64, nb1 + 1 * 64,
                                               nw2 + 1 * 4096, nb2 + 1 * 64,
                                               ew1 + 2 * 129 * 64, eb1 + 2 * 64);

    // ---- layer 2: agg/node dead, write x' straight to d_out ----
    cudaMemcpyAsync(out, pxA, XB, cudaMemcpyDeviceToDevice, 0);
    edge_kernel<<<EGRID, 128, EDGE_SMEM_BYTES>>>(pxA, out, ei,
        ew1 + 2 * 129 * 64 + 128 * 64, ew2 + 2 * 4096, eb2 + 2 * 64,
        cw1 + 2 * 4096, cb1 + 2 * 64, cw2 + 2 * 64, cb2 + 2, 0);
}

// round 10
// speedup vs baseline: 2.2373x; 1.2626x over previous
#include <cuda_runtime.h>
#include <cuda_bf16.h>
#include <cstdint>

#define N_NODES 100000
#define N_EDGES 1600000
#define HID 64
#define NGROUPS (N_EDGES / 32)       // 50000
#define NODE_GROUPS (N_NODES / 32)   // 3125

typedef unsigned long long ull;

// ---------- device scratch ----------
__device__ float g_h[N_NODES * HID];
__device__ float g_agg[N_NODES * HID];
__device__ float g_P[N_NODES * HID];
__device__ float g_Q[N_NODES * HID];
__device__ float g_xA[N_NODES * 3];
__device__ float g_xB[N_NODES * 3];

// ---------- helpers ----------
__device__ __forceinline__ float silu(float v) {
    float u = 0.5f * v, th;
    asm("tanh.approx.f32 %0, %1;" : "=f"(th) : "f"(u));
    return v * fmaf(th, 0.5f, 0.5f);
}
__device__ __forceinline__ void red_add_v4(float* addr, float a, float b, float c, float d) {
    asm volatile("red.global.add.v4.f32 [%0], {%1, %2, %3, %4};"
                 :: "l"(addr), "f"(a), "f"(b), "f"(c), "f"(d) : "memory");
}
__device__ __forceinline__ void bf16_split2(float f0, float f1, uint32_t& hi, uint32_t& lo) {
    uint32_t h;
    asm("cvt.rn.bf16x2.f32 %0, %1, %2;" : "=r"(h) : "f"(f1), "f"(f0));
    float h0 = __uint_as_float(h << 16);
    float h1 = __uint_as_float(h & 0xffff0000u);
    float l0 = f0 - h0, l1 = f1 - h1;
    uint32_t l;
    asm("cvt.rn.bf16x2.f32 %0, %1, %2;" : "=r"(l) : "f"(l1), "f"(l0));
    hi = h; lo = l;
}
__device__ __forceinline__ uint32_t bf16_pack2(float f0, float f1) {
    uint32_t h;
    asm("cvt.rn.bf16x2.f32 %0, %1, %2;" : "=r"(h) : "f"(f1), "f"(f0));
    return h;
}
__device__ __forceinline__ void mma16816(float c[4], const uint32_t a[4],
                                         uint32_t b0, uint32_t b1) {
    asm volatile(
        "mma.sync.aligned.m16n8k16.row.col.f32.bf16.bf16.f32 "
        "{%0,%1,%2,%3}, {%4,%5,%6,%7}, {%8,%9}, {%0,%1,%2,%3};"
        : "+f"(c[0]), "+f"(c[1]), "+f"(c[2]), "+f"(c[3])
        : "r"(a[0]), "r"(a[1]), "r"(a[2]), "r"(a[3]), "r"(b0), "r"(b1));
}
// stage a 64x64 fp32 weight as bf16 hi/lo B-tiles [n][kk], stride 36
__device__ __forceinline__ void stage_btile(uint32_t* dhi, uint32_t* dlo,
                                            const float* __restrict__ W, int tid, int nth) {
    for (int i = tid; i < 2048; i += nth) {
        int n = i >> 5, kk = i & 31;
        uint32_t hi, lo;
        bf16_split2(W[(2 * kk) * 64 + n], W[(2 * kk + 1) * 64 + n], hi, lo);
        dhi[n * 36 + kk] = hi;
        dlo[n * 36 + kk] = lo;
    }
}
// stage hi-only B-tile (2-term path)
__device__ __forceinline__ void stage_btile_hi(uint32_t* dhi,
                                               const float* __restrict__ W, int tid, int nth) {
    for (int i = tid; i < 2048; i += nth) {
        int n = i >> 5, kk = i & 31;
        dhi[n * 36 + kk] = bf16_pack2(W[(2 * kk) * 64 + n], W[(2 * kk + 1) * 64 + n]);
    }
}
// 3-term K=64 mma, A from smem
__device__ __forceinline__ void mma3_smem(float acc[16][4],
                                          const uint32_t* __restrict__ Ah,
                                          const uint32_t* __restrict__ Al,
                                          const uint32_t* __restrict__ Bh,
                                          const uint32_t* __restrict__ Bl,
                                          int g, int t) {
    #pragma unroll
    for (int kt = 0; kt < 4; kt++) {
        uint32_t ah[2][4], al[2][4];
        #pragma unroll
        for (int mt = 0; mt < 2; mt++) {
            int rb = (16 * mt + g) * 36 + 8 * kt + t;
            ah[mt][0] = Ah[rb];     ah[mt][1] = Ah[rb + 8 * 36];
            ah[mt][2] = Ah[rb + 4]; ah[mt][3] = Ah[rb + 8 * 36 + 4];
            al[mt][0] = Al[rb];     al[mt][1] = Al[rb + 8 * 36];
            al[mt][2] = Al[rb + 4]; al[mt][3] = Al[rb + 8 * 36 + 4];
        }
        #pragma unroll
        for (int nt = 0; nt < 8; nt++) {
            int bi = (8 * nt + g) * 36 + 8 * kt + t;
            uint32_t bh0 = Bh[bi], bh1 = Bh[bi + 4];
            uint32_t bl0 = Bl[bi], bl1 = Bl[bi + 4];
            #pragma unroll
            for (int mt = 0; mt < 2; mt++) {
                mma16816(acc[mt * 8 + nt], ah[mt], bh0, bh1);
                mma16816(acc[mt * 8 + nt], ah[mt], bl0, bl1);
                mma16816(acc[mt * 8 + nt], al[mt], bh0, bh1);
            }
        }
    }
}
// 3-term K=64 mma, A from register fragments
__device__ __forceinline__ void mma3_reg(float acc[16][4],
                                         const uint32_t fh[2][4][4],
                                         const uint32_t fl[2][4][4],
                                         const uint32_t* __restrict__ Bh,
                                         const uint32_t* __restrict__ Bl,
                                         int g, int t) {
    #pragma unroll
    for (int kt = 0; kt < 4; kt++) {
        #pragma unroll
        for (int nt = 0; nt < 8; nt++) {
            int bi = (8 * nt + g) * 36 + 8 * kt + t;
            uint32_t bh0 = Bh[bi], bh1 = Bh[bi + 4];
            uint32_t bl0 = Bl[bi], bl1 = Bl[bi + 4];
            #pragma unroll
            for (int mt = 0; mt < 2; mt++) {
                mma16816(acc[mt * 8 + nt], fh[mt][kt], bh0, bh1);
                mma16816(acc[mt * 8 + nt], fh[mt][kt], bl0, bl1);
                mma16816(acc[mt * 8 + nt], fl[mt][kt], bh0, bh1);
            }
        }
    }
}
// 2-term K=64 mma (Ah*Bh + Al*Bh), A from smem, B single bf16
__device__ __forceinline__ void mma2_smem(float acc[16][4],
                                          const uint32_t* __restrict__ Ah,
                                          const uint32_t* __restrict__ Al,
                                          const uint32_t* __restrict__ Bh,
                                          int g, int t) {
    #pragma unroll
    for (int kt = 0; kt < 4; kt++) {
        uint32_t ah[2][4], al[2][4];
        #pragma unroll
        for (int mt = 0; mt < 2; mt++) {
            int rb = (16 * mt + g) * 36 + 8 * kt + t;
            ah[mt][0] = Ah[rb];     ah[mt][1] = Ah[rb + 8 * 36];
            ah[mt][2] = Ah[rb + 4]; ah[mt][3] = Ah[rb + 8 * 36 + 4];
            al[mt][0] = Al[rb];     al[mt][1] = Al[rb + 8 * 36];
            al[mt][2] = Al[rb + 4]; al[mt][3] = Al[rb + 8 * 36 + 4];
        }
        #pragma unroll
        for (int nt = 0; nt < 8; nt++) {
            int bi = (8 * nt + g) * 36 + 8 * kt + t;
            uint32_t bh0 = Bh[bi], bh1 = Bh[bi + 4];
            #pragma unroll
            for (int mt = 0; mt < 2; mt++) {
                mma16816(acc[mt * 8 + nt], ah[mt], bh0, bh1);
                mma16816(acc[mt * 8 + nt], al[mt], bh0, bh1);
            }
        }
    }
}
// 2-term K=64 mma, A from register fragments
__device__ __forceinline__ void mma2_reg(float acc[16][4],
                                         const uint32_t fh[2][4][4],
                                         const uint32_t fl[2][4][4],
                                         const uint32_t* __restrict__ Bh,
                                         int g, int t) {
    #pragma unroll
    for (int kt = 0; kt < 4; kt++) {
        #pragma unroll
        for (int nt = 0; nt < 8; nt++) {
            int bi = (8 * nt + g) * 36 + 8 * kt + t;
            uint32_t bh0 = Bh[bi], bh1 = Bh[bi + 4];
            #pragma unroll
            for (int mt = 0; mt < 2; mt++) {
                mma16816(acc[mt * 8 + nt], fh[mt][kt], bh0, bh1);
                mma16816(acc[mt * 8 + nt], fl[mt][kt], bh0, bh1);
            }
        }
    }
}

// ---------- init ----------
__global__ void init_kernel(const int* __restrict__ z, const float* __restrict__ emb,
                            const float* __restrict__ t,
                            const float* __restrict__ tw1, const float* __restrict__ tb1,
                            const float* __restrict__ tw2, const float* __restrict__ tb2,
                            int B) {
    __shared__ float s1[HID];
    __shared__ float tm[HID];
    int tidb = threadIdx.x;
    if (tidb < HID) {
        float w = tw1[tidb], bb = tb1[tidb];
        float acc = 0.f;
        for (int b = 0; b < B; b++) acc += silu(t[b] * w + bb);
        s1[tidb] = acc / (float)B;
    }
    __syncthreads();
    if (tidb < HID) {
        float o = tb2[tidb];
        for (int k = 0; k < HID; k++) o += s1[k] * tw2[k * HID + tidb];
        tm[tidb] = o;
    }
    __syncthreads();
    int i = blockIdx.x * blockDim.x + tidb;
    if (i < N_NODES * HID) {
        int node = i >> 6, j = i & 63;
        g_h[i] = emb[z[node] * HID + j] + tm[j];
        g_agg[i] = 0.f;
    }
}

// dummy launch to align ncu capture (-s 5) onto an edge kernel
__global__ void dummy_kernel() {}

// ---------- pre kernel (layer 0 only): P = h@W1a + b1, Q = h@W1b (3-term) ----------
#define PW_AH 0
#define PW_AL 2304
#define PW_BH 4608
#define PW_BL 6912
#define P_B1W 9216
#define P_WBASE 9280
#define P_WW 2304
#define P_SMEM_WORDS (P_WBASE + 6 * P_WW)
#define P_SMEM_BYTES (P_SMEM_WORDS * 4)

__global__ void __launch_bounds__(192)
pre_kernel(const float* __restrict__ ew1, const float* __restrict__ eb1g) {
    extern __shared__ uint32_t smw[];
    float* smf = (float*)smw;
    const int tid = threadIdx.x;

    stage_btile(smw + PW_AH, smw + PW_AL, ew1, tid, 192);
    stage_btile(smw + PW_BH, smw + PW_BL, ew1 + 64 * 64, tid, 192);
    if (tid < 64) smf[P_B1W + tid] = eb1g[tid];
    __syncthreads();

    const int lane = tid & 31;
    const int wrp = tid >> 5;
    const int g = lane >> 2;
    const int t = lane & 3;
    uint32_t* Ah = smw + P_WBASE + wrp * P_WW;
    uint32_t* Al = Ah + 1152;

    const int gwarp = (blockIdx.x * 192 + tid) >> 5;
    const int nwarps = (gridDim.x * 192) >> 5;

    for (int grp = gwarp; grp < NODE_GROUPS; grp += nwarps) {
        const int base = grp * 32;
        __syncwarp();
        #pragma unroll 4
        for (int e2 = 0; e2 < 32; e2++) {
            float2 hv = __ldg((const float2*)(g_h + (size_t)(base + e2) * 64 + 2 * lane));
            uint32_t hi, lo;
            bf16_split2(hv.x, hv.y, hi, lo);
            Ah[e2 * 36 + lane] = hi;
            Al[e2 * 36 + lane] = lo;
        }
        __syncwarp();

        float accP[16][4], accQ[16][4];
        #pragma unroll
        for (int nt = 0; nt < 8; nt++) {
            float2 bb = *(const float2*)(smf + P_B1W + 8 * nt + 2 * t);
            #pragma unroll
            for (int mt = 0; mt < 2; mt++) {
                accP[mt * 8 + nt][0] = bb.x; accP[mt * 8 + nt][1] = bb.y;
                accP[mt * 8 + nt][2] = bb.x; accP[mt * 8 + nt][3] = bb.y;
                accQ[mt * 8 + nt][0] = 0.f; accQ[mt * 8 + nt][1] = 0.f;
                accQ[mt * 8 + nt][2] = 0.f; accQ[mt * 8 + nt][3] = 0.f;
            }
        }
        mma3_smem(accP, Ah, Al, smw + PW_AH, smw + PW_AL, g, t);
        mma3_smem(accQ, Ah, Al, smw + PW_BH, smw + PW_BL, g, t);
        #pragma unroll
        for (int mt = 0; mt < 2; mt++) {
            int r1 = base + 16 * mt + g;
            int r2 = r1 + 8;
            #pragma unroll
            for (int nt = 0; nt < 8; nt++) {
                int c = 8 * nt + 2 * t;
                *(float2*)(g_P + (size_t)r1 * 64 + c) = make_float2(accP[mt * 8 + nt][0], accP[mt * 8 + nt][1]);
                *(float2*)(g_P + (size_t)r2 * 64 + c) = make_float2(accP[mt * 8 + nt][2], accP[mt * 8 + nt][3]);
                *(float2*)(g_Q + (size_t)r1 * 64 + c) = make_float2(accQ[mt * 8 + nt][0], accQ[mt * 8 + nt][1]);
                *(float2*)(g_Q + (size_t)r2 * 64 + c) = make_float2(accQ[mt * 8 + nt][2], accQ[mt * 8 + nt][3]);
            }
        }
    }
}

// ---------- edge kernel (2-term mma, 3 CTAs/SM) ----------
#define B_W2HI 0
#define B_C1HI 2304
#define SC_W1C 4608
#define SC_B2  4672
#define SC_CB1 4736
#define SC_CW2 4800
#define SC_CB2 4864
#define WARP_BASE 4868
#define WARP_W 2304          // Ah 1152 + Al 1152
#define EDGE_SMEM_WORDS (WARP_BASE + 4 * WARP_W)
#define EDGE_SMEM_BYTES (EDGE_SMEM_WORDS * 4)   // 56,336 B -> 3 CTAs/SM

__global__ void __launch_bounds__(128, 3)
edge_kernel(const float* __restrict__ x, float* __restrict__ xn,
            const int* __restrict__ ei,
            const float* __restrict__ w1c_g,
            const float* __restrict__ ew2, const float* __restrict__ eb2g,
            const float* __restrict__ cw1, const float* __restrict__ cb1g,
            const float* __restrict__ cw2g, const float* __restrict__ cb2g,
            int do_agg) {
    extern __shared__ uint32_t smw[];
    float* smf = (float*)smw;
    const int tid = threadIdx.x;

    stage_btile_hi(smw + B_W2HI, ew2, tid, 128);
    stage_btile_hi(smw + B_C1HI, cw1, tid, 128);
    if (tid < 64) {
        smf[SC_W1C + tid] = w1c_g[tid];
        smf[SC_B2 + tid]  = eb2g[tid];
        smf[SC_CB1 + tid] = cb1g[tid];
        smf[SC_CW2 + tid] = cw2g[tid];
    }
    if (tid == 0) smf[SC_CB2] = cb2g[0];
    __syncthreads();

    const int lane = tid & 31;
    const int wrp = tid >> 5;
    const int g = lane >> 2;
    const int t = lane & 3;
    uint32_t* Ah = smw + WARP_BASE + wrp * WARP_W;
    uint32_t* Al = Ah + 1152;
    const float w1c0 = smf[SC_W1C + 2 * lane];
    const float w1c1 = smf[SC_W1C + 2 * lane + 1];
    const float cb2s = smf[SC_CB2];

    const int gwarp = (blockIdx.x * 128 + tid) >> 5;
    const int nwarps = (gridDim.x * 128) >> 5;

    int grp = gwarp;
    int s_n = 0, d_n = 0;
    float xs0 = 0, xs1 = 0, xs2 = 0, xd0 = 0, xd1 = 0, xd2 = 0;
    if (grp < NGROUPS) {
        int e = grp * 32 + lane;
        s_n = ei[e]; d_n = ei[N_EDGES + e];
        xs0 = __ldg(&x[s_n * 3 + 0]); xs1 = __ldg(&x[s_n * 3 + 1]); xs2 = __ldg(&x[s_n * 3 + 2]);
        xd0 = __ldg(&x[d_n * 3 + 0]); xd1 = __ldg(&x[d_n * 3 + 1]); xd2 = __ldg(&x[d_n * 3 + 2]);
    }

    for (; grp < NGROUPS; grp += nwarps) {
        const int s = s_n, d = d_n;
        const float dx0 = xd0 - xs0;
        const float dx1 = xd1 - xs1;
        const float dx2 = xd2 - xs2;
        const float r2 = dx0 * dx0 + dx1 * dx1 + dx2 * dx2;

        __syncwarp();
        #pragma unroll 4
        for (int e2 = 0; e2 < 32; e2++) {
            int nd = __shfl_sync(0xffffffffu, d, e2);
            int ns = __shfl_sync(0xffffffffu, s, e2);
            float rr = __shfl_sync(0xffffffffu, r2, e2);
            float2 pv = __ldg((const float2*)(g_P + (size_t)nd * 64 + 2 * lane));
            float2 qv = __ldg((const float2*)(g_Q + (size_t)ns * 64 + 2 * lane));
            float f0 = silu(fmaf(rr, w1c0, pv.x + qv.x));
            float f1 = silu(fmaf(rr, w1c1, pv.y + qv.y));
            uint32_t hi, lo;
            bf16_split2(f0, f1, hi, lo);
            Ah[e2 * 36 + lane] = hi;
            Al[e2 * 36 + lane] = lo;
        }
        __syncwarp();

        {
            int gn = grp + nwarps;
            if (gn < NGROUPS) {
                int e = gn * 32 + lane;
                s_n = ei[e]; d_n = ei[N_EDGES + e];
                xs0 = __ldg(&x[s_n * 3 + 0]); xs1 = __ldg(&x[s_n * 3 + 1]); xs2 = __ldg(&x[s_n * 3 + 2]);
                xd0 = __ldg(&x[d_n * 3 + 0]); xd1 = __ldg(&x[d_n * 3 + 1]); xd2 = __ldg(&x[d_n * 3 + 2]);
            }
        }

        // ---- matmul1: D = ef1 @ W2 + b2 (2-term) ----
        float acc[16][4];
        #pragma unroll
        for (int nt = 0; nt < 8; nt++) {
            float2 bb = *(const float2*)(smf + SC_B2 + 8 * nt + 2 * t);
            #pragma unroll
            for (int mt = 0; mt < 2; mt++) {
                acc[mt * 8 + nt][0] = bb.x; acc[mt * 8 + nt][1] = bb.y;
                acc[mt * 8 + nt][2] = bb.x; acc[mt * 8 + nt][3] = bb.y;
            }
        }
        mma2_smem(acc, Ah, Al, smw + B_W2HI, g, t);

        // ---- m = silu(D); paired red.v4; to matmul2 A frags ----
        uint32_t mh[2][4][4], ml[2][4][4];
        int dtop[2], dbot[2];
        #pragma unroll
        for (int mt = 0; mt < 2; mt++) {
            dtop[mt] = __shfl_sync(0xffffffffu, d, 16 * mt + g);
            dbot[mt] = __shfl_sync(0xffffffffu, d, 16 * mt + g + 8);
        }
        const int colbase_off = 2 * (t & ~1);
        #pragma unroll
        for (int mt = 0; mt < 2; mt++) {
            #pragma unroll
            for (int nt = 0; nt < 8; nt++) {
                float v0 = silu(acc[mt * 8 + nt][0]);
                float v1 = silu(acc[mt * 8 + nt][1]);
                float v2 = silu(acc[mt * 8 + nt][2]);
                float v3 = silu(acc[mt * 8 + nt][3]);
                if (do_agg) {
                    float px = (t & 1) ? v0 : v2;
                    float qx = (t & 1) ? v1 : v3;
                    float pr = __shfl_xor_sync(0xffffffffu, px, 1);
                    float qr = __shfl_xor_sync(0xffffffffu, qx, 1);
                    int row = (t & 1) ? dbot[mt] : dtop[mt];
                    int col = 8 * nt + colbase_off;
                    float a0 = (t & 1) ? pr : v0;
                    float a1 = (t & 1) ? qr : v1;
                    float a2 = (t & 1) ? v2 : pr;
                    float a3 = (t & 1) ? v3 : qr;
                    red_add_v4(&g_agg[(size_t)row * 64 + col], a0, a1, a2, a3);
                }
                int kt = nt >> 1, o = (nt & 1) * 2;
                bf16_split2(v0, v1, mh[mt][kt][o], ml[mt][kt][o]);
                bf16_split2(v2, v3, mh[mt][kt][o + 1], ml[mt][kt][o + 1]);
            }
        }

        // ---- matmul2: D2 = m @ C1 + cb1 (2-term) ----
        float acc2[16][4];
        #pragma unroll
        for (int nt = 0; nt < 8; nt++) {
            float2 bb = *(const float2*)(smf + SC_CB1 + 8 * nt + 2 * t);
            #pragma unroll
            for (int mt = 0; mt < 2; mt++) {
                acc2[mt * 8 + nt][0] = bb.x; acc2[mt * 8 + nt][1] = bb.y;
                acc2[mt * 8 + nt][2] = bb.x; acc2[mt * 8 + nt][3] = bb.y;
            }
        }
        mma2_reg(acc2, mh, ml, smw + B_C1HI, g, t);

        // ---- coord epilogue ----
        float pr0 = 0.f, pr1 = 0.f, pr2 = 0.f, pr3 = 0.f;
        #pragma unroll
        for (int nt = 0; nt < 8; nt++) {
            float2 cwv = *(const float2*)(smf + SC_CW2 + 8 * nt + 2 * t);
            pr0 = fmaf(silu(acc2[nt][0]), cwv.x, pr0);
            pr0 = fmaf(silu(acc2[nt][1]), cwv.y, pr0);
            pr1 = fmaf(silu(acc2[nt][2]), cwv.x, pr1);
            pr1 = fmaf(silu(acc2[nt][3]), cwv.y, pr1);
            pr2 = fmaf(silu(acc2[8 + nt][0]), cwv.x, pr2);
            pr2 = fmaf(silu(acc2[8 + nt][1]), cwv.y, pr2);
            pr3 = fmaf(silu(acc2[8 + nt][2]), cwv.x, pr3);
            pr3 = fmaf(silu(acc2[8 + nt][3]), cwv.y, pr3);
        }
        pr0 += __shfl_xor_sync(0xffffffffu, pr0, 1);
        pr0 += __shfl_xor_sync(0xffffffffu, pr0, 2);
        pr1 += __shfl_xor_sync(0xffffffffu, pr1, 1);
        pr1 += __shfl_xor_sync(0xffffffffu, pr1, 2);
        pr2 += __shfl_xor_sync(0xffffffffu, pr2, 1);
        pr2 += __shfl_xor_sync(0xffffffffu, pr2, 2);
        pr3 += __shfl_xor_sync(0xffffffffu, pr3, 1);
        pr3 += __shfl_xor_sync(0xffffffffu, pr3, 2);
        float p = (t == 0) ? pr0 : (t == 1) ? pr1 : (t == 2) ? pr2 : pr3;
        const int e2l = g + 8 * t;
        p += cb2s;
        int dd = __shfl_sync(0xffffffffu, d, e2l);
        float ddx0 = __shfl_sync(0xffffffffu, dx0, e2l);
        float ddx1 = __shfl_sync(0xffffffffu, dx1, e2l);
        float ddx2 = __shfl_sync(0xffffffffu, dx2, e2l);
        atomicAdd(&xn[dd * 3 + 0], ddx0 * p);
        atomicAdd(&xn[dd * 3 + 1], ddx1 * p);
        atomicAdd(&xn[dd * 3 + 2], ddx2 * p);
    }
}

// ---------- node kernel (mma.sync, 3-term) + fused next-layer P/Q ----------
#define N_W1HH 0
#define N_W1HL 2304
#define N_W1AH 4608
#define N_W1AL 6912
#define N_W2H  9216
#define N_W2L  11520
#define N_PAH  13824
#define N_PAL  16128
#define N_PBH  18432
#define N_PBL  20736
#define N_B1W  23040
#define N_B2W  23104
#define N_EB1W 23168
#define N_ABASE 23232
#define N_AW   2304
#define NODE_SMEM_WORDS (N_ABASE + 8 * N_AW)
#define NODE_SMEM_BYTES (NODE_SMEM_WORDS * 4)

__global__ void __launch_bounds__(256)
node_kernel(const float* __restrict__ nw1, const float* __restrict__ nb1g,
            const float* __restrict__ nw2, const float* __restrict__ nb2g,
            const float* __restrict__ ew1n, const float* __restrict__ eb1n) {
    extern __shared__ uint32_t smw[];
    float* smf = (float*)smw;
    const int tid = threadIdx.x;

    stage_btile(smw + N_W1HH, smw + N_W1HL, nw1, tid, 256);
    stage_btile(smw + N_W1AH, smw + N_W1AL, nw1 + 64 * 64, tid, 256);
    stage_btile(smw + N_W2H, smw + N_W2L, nw2, tid, 256);
    stage_btile(smw + N_PAH, smw + N_PAL, ew1n, tid, 256);
    stage_btile(smw + N_PBH, smw + N_PBL, ew1n + 64 * 64, tid, 256);
    if (tid < 64) {
        smf[N_B1W + tid]  = nb1g[tid];
        smf[N_B2W + tid]  = nb2g[tid];
        smf[N_EB1W + tid] = eb1n[tid];
    }
    __syncthreads();

    const int lane = tid & 31;
    const int wrp = tid >> 5;
    const int g = lane >> 2;
    const int t = lane & 3;
    uint32_t* Ah = smw + N_ABASE + wrp * N_AW;
    uint32_t* Al = Ah + 1152;

    const int gwarp = (blockIdx.x * 256 + tid) >> 5;
    const int nwarps = (gridDim.x * 256) >> 5;

    for (int grp = gwarp; grp < NODE_GROUPS; grp += nwarps) {
        const int base = grp * 32;

        __syncwarp();
        #pragma unroll 4
        for (int e2 = 0; e2 < 32; e2++) {
            float2 hv = __ldg((const float2*)(g_h + (size_t)(base + e2) * 64 + 2 * lane));
            uint32_t hi, lo;
            bf16_split2(hv.x, hv.y, hi, lo);
            Ah[e2 * 36 + lane] = hi;
            Al[e2 * 36 + lane] = lo;
        }
        __syncwarp();

        float acc1[16][4];
        #pragma unroll
        for (int nt = 0; nt < 8; nt++) {
            float2 bb = *(const float2*)(smf + N_B1W + 8 * nt + 2 * t);
            #pragma unroll
            for (int mt = 0; mt < 2; mt++) {
                acc1[mt * 8 + nt][0] = bb.x; acc1[mt * 8 + nt][1] = bb.y;
                acc1[mt * 8 + nt][2] = bb.x; acc1[mt * 8 + nt][3] = bb.y;
            }
        }
        mma3_smem(acc1, Ah, Al, smw + N_W1HH, smw + N_W1HL, g, t);

        __syncwarp();
        #pragma unroll 4
        for (int e2 = 0; e2 < 32; e2++) {
            float2* ap = (float2*)(g_agg + (size_t)(base + e2) * 64 + 2 * lane);
            float2 av = *ap;
            *ap = make_float2(0.f, 0.f);
            uint32_t hi, lo;
            bf16_split2(av.x, av.y, hi, lo);
            Ah[e2 * 36 + lane] = hi;
            Al[e2 * 36 + lane] = lo;
        }
        __syncwarp();
        mma3_smem(acc1, Ah, Al, smw + N_W1AH, smw + N_W1AL, g, t);

        uint32_t mh[2][4][4], ml[2][4][4];
        #pragma unroll
        for (int mt = 0; mt < 2; mt++) {
            #pragma unroll
            for (int nt = 0; nt < 8; nt++) {
                float v0 = silu(acc1[mt * 8 + nt][0]);
                float v1 = silu(acc1[mt * 8 + nt][1]);
                float v2 = silu(acc1[mt * 8 + nt][2]);
                float v3 = silu(acc1[mt * 8 + nt][3]);
                int kt = nt >> 1, o = (nt & 1) * 2;
                bf16_split2(v0, v1, mh[mt][kt][o], ml[mt][kt][o]);
                bf16_split2(v2, v3, mh[mt][kt][o + 1], ml[mt][kt][o + 1]);
            }
        }

        float acc2[16][4];
        #pragma unroll
        for (int nt = 0; nt < 8; nt++) {
            float2 bb = *(const float2*)(smf + N_B2W + 8 * nt + 2 * t);
            #pragma unroll
            for (int mt = 0; mt < 2; mt++) {
                acc2[mt * 8 + nt][0] = bb.x; acc2[mt * 8 + nt][1] = bb.y;
                acc2[mt * 8 + nt][2] = bb.x; acc2[mt * 8 + nt][3] = bb.y;
            }
        }
        mma3_reg(acc2, mh, ml, smw + N_W2H, smw + N_W2L, g, t);

        uint32_t hh[2][4][4], hl[2][4][4];
        #pragma unroll
        for (int mt = 0; mt < 2; mt++) {
            int r1 = base + 16 * mt + g;
            int r2 = r1 + 8;
            #pragma unroll
            for (int nt = 0; nt < 8; nt++) {
                int c = 8 * nt + 2 * t;
                float2 h1 = __ldg((const float2*)(g_h + (size_t)r1 * 64 + c));
                float2 h2 = __ldg((const float2*)(g_h + (size_t)r2 * 64 + c));
                float v0 = h1.x + acc2[mt * 8 + nt][0];
                float v1 = h1.y + acc2[mt * 8 + nt][1];
                float v2 = h2.x + acc2[mt * 8 + nt][2];
                float v3 = h2.y + acc2[mt * 8 + nt][3];
                *(float2*)(g_h + (size_t)r1 * 64 + c) = make_float2(v0, v1);
                *(float2*)(g_h + (size_t)r2 * 64 + c) = make_float2(v2, v3);
                int kt = nt >> 1, o = (nt & 1) * 2;
                bf16_split2(v0, v1, hh[mt][kt][o], hl[mt][kt][o]);
                bf16_split2(v2, v3, hh[mt][kt][o + 1], hl[mt][kt][o + 1]);
            }
        }

        float accp[16][4];
        #pragma unroll
        for (int nt = 0; nt < 8; nt++) {
            float2 bb = *(const float2*)(smf + N_EB1W + 8 * nt + 2 * t);
            #pragma unroll
            for (int mt = 0; mt < 2; mt++) {
                accp[mt * 8 + nt][0] = bb.x; accp[mt * 8 + nt][1] = bb.y;
                accp[mt * 8 + nt][2] = bb.x; accp[mt * 8 + nt][3] = bb.y;
            }
        }
        mma3_reg(accp, hh, hl, smw + N_PAH, smw + N_PAL, g, t);
        #pragma unroll
        for (int mt = 0; mt < 2; mt++) {
            int r1 = base + 16 * mt + g;
            int r2 = r1 + 8;
            #pragma unroll
            for (int nt = 0; nt < 8; nt++) {
                int c = 8 * nt + 2 * t;
                *(float2*)(g_P + (size_t)r1 * 64 + c) = make_float2(accp[mt * 8 + nt][0], accp[mt * 8 + nt][1]);
                *(float2*)(g_P + (size_t)r2 * 64 + c) = make_float2(accp[mt * 8 + nt][2], accp[mt * 8 + nt][3]);
            }
        }

        #pragma unroll
        for (int a = 0; a < 16; a++) {
            accp[a][0] = 0.f; accp[a][1] = 0.f; accp[a][2] = 0.f; accp[a][3] = 0.f;
        }
        mma3_reg(accp, hh, hl, smw + N_PBH, smw + N_PBL, g, t);
        #pragma unroll
        for (int mt = 0; mt < 2; mt++) {
            int r1 = base + 16 * mt + g;
            int r2 = r1 + 8;
            #pragma unroll
            for (int nt = 0; nt < 8; nt++) {
                int c = 8 * nt + 2 * t;
                *(float2*)(g_Q + (size_t)r1 * 64 + c) = make_float2(accp[mt * 8 + nt][0], accp[mt * 8 + nt][1]);
                *(float2*)(g_Q + (size_t)r2 * 64 + c) = make_float2(accp[mt * 8 + nt][2], accp[mt * 8 + nt][3]);
            }
        }
    }
}

// ---------- launch ----------
extern "C" void kernel_launch(void* const* d_in, const int* in_sizes, int n_in,
                              void* d_out, int out_size) {
    const float* x   = (const float*)d_in[0];
    const int*   z   = (const int*)d_in[1];
    const float* t   = (const float*)d_in[2];
    const int*   ei  = (const int*)d_in[3];
    const float* emb = (const float*)d_in[4];
    const float* tw1 = (const float*)d_in[5];
    const float* tb1 = (const float*)d_in[6];
    const float* tw2 = (const float*)d_in[7];
    const float* tb2 = (const float*)d_in[8];
    const float* ew1 = (const float*)d_in[9];
    const float* eb1 = (const float*)d_in[10];
    const float* ew2 = (const float*)d_in[11];
    const float* eb2 = (const float*)d_in[12];
    const float* cw1 = (const float*)d_in[13];
    const float* cb1 = (const float*)d_in[14];
    const float* cw2 = (const float*)d_in[15];
    const float* cb2 = (const float*)d_in[16];
    const float* nw1 = (const float*)d_in[17];
    const float* nb1 = (const float*)d_in[18];
    const float* nw2 = (const float*)d_in[19];
    const float* nb2 = (const float*)d_in[20];
    float* out = (float*)d_out;
    const int B = in_sizes[2];

    float *pxA, *pxB;
    cudaGetSymbolAddress((void**)&pxA, g_xA);
    cudaGetSymbolAddress((void**)&pxB, g_xB);

    cudaFuncSetAttribute(edge_kernel, cudaFuncAttributeMaxDynamicSharedMemorySize, EDGE_SMEM_BYTES);
    cudaFuncSetAttribute(node_kernel, cudaFuncAttributeMaxDynamicSharedMemorySize, NODE_SMEM_BYTES);
    cudaFuncSetAttribute(pre_kernel,  cudaFuncAttributeMaxDynamicSharedMemorySize, P_SMEM_BYTES);

    const size_t XB = (size_t)N_NODES * 3 * sizeof(float);
    const int EGRID = 456;   // 3 CTAs/SM x 152

    // launches: 0 init, 1 pre, 2 edge0, 3 node0, 4 dummy, 5 edge1 (ncu -s 5 target)
    init_kernel<<<(N_NODES * HID + 255) / 256, 256>>>(z, emb, t, tw1, tb1, tw2, tb2, B);

    // ---- layer 0 ----
    pre_kernel<<<304, 192, P_SMEM_BYTES>>>(ew1 + 0 * 129 * 64, eb1 + 0 * 64);
    cudaMemcpyAsync(pxB, x, XB, cudaMemcpyDeviceToDevice, 0);
    edge_kernel<<<EGRID, 128, EDGE_SMEM_BYTES>>>(x, pxB, ei,
        ew1 + 0 * 129 * 64 + 128 * 64, ew2 + 0 * 4096, eb2 + 0 * 64,
        cw1 + 0 * 4096, cb1 + 0 * 64, cw2 + 0 * 64, cb2 + 0, 1);
    node_kernel<<<152, 256, NODE_SMEM_BYTES>>>(nw1 + 0 * 128 * 64, nb1 + 0 * 64,
                                               nw2 + 0 * 4096, nb2 + 0 * 64,
                                               ew1 + 1 * 129 * 64, eb1 + 1 * 64);
    dummy_kernel<<<1, 32>>>();

    // ---- layer 1 ----
    cudaMemcpyAsync(pxA, pxB, XB, cudaMemcpyDeviceToDevice, 0);
    edge_kernel<<<EGRID, 128, EDGE_SMEM_BYTES>>>(pxB, pxA, ei,
        ew1 + 1 * 129 * 64 + 128 * 64, ew2 + 1 * 4096, eb2 + 1 * 64,
        cw1 + 1 * 4096, cb1 + 1 * 64, cw2 + 1 * 64, cb2 + 1, 1);
    node_kernel<<<152, 256, NODE_SMEM_BYTES>>>(nw1 + 1 * 128 * 64, nb1 + 1 * 64,
                                               nw2 + 1 * 4096, nb2 + 1 * 64,
                                               ew1 + 2 * 129 * 64, eb1 + 2 * 64);

    // ---- layer 2: agg/node dead, write x' straight to d_out ----
    cudaMemcpyAsync(out, pxA, XB, cudaMemcpyDeviceToDevice, 0);
    edge_kernel<<<EGRID, 128, EDGE_SMEM_BYTES>>>(pxA, out, ei,
        ew1 + 2 * 129 * 64 + 128 * 64, ew2 + 2 * 4096, eb2 + 2 * 64,
        cw1 + 2 * 4096, cb1 + 2 * 64, cw2 + 2 * 64, cb2 + 2, 0);
}

// round 11
// speedup vs baseline: 2.7114x; 1.2119x over previous
#include <cuda_runtime.h>
#include <cuda_fp16.h>
#include <cstdint>

#define N_NODES 100000
#define N_EDGES 1600000
#define HID 64
#define NGROUPS (N_EDGES / 32)       // 50000
#define NODE_GROUPS (N_NODES / 32)   // 3125

// ---------- device scratch ----------
__device__ float g_h[N_NODES * HID];
__device__ float g_agg[N_NODES * HID];
__device__ float g_P[N_NODES * HID];
__device__ float g_Q[N_NODES * HID];
__device__ float g_xA[N_NODES * 3];
__device__ float g_xB[N_NODES * 3];

// ---------- helpers ----------
__device__ __forceinline__ float silu(float v) {
    float u = 0.5f * v, th;
    asm("tanh.approx.f32 %0, %1;" : "=f"(th) : "f"(u));
    return v * fmaf(th, 0.5f, 0.5f);
}
__device__ __forceinline__ void red_add_v4(float* addr, float a, float b, float c, float d) {
    asm volatile("red.global.add.v4.f32 [%0], {%1, %2, %3, %4};"
                 :: "l"(addr), "f"(a), "f"(b), "f"(c), "f"(d) : "memory");
}
// pack two floats to f16x2 (lo = f0, hi = f1)
__device__ __forceinline__ uint32_t f16_pack2(float f0, float f1) {
    uint32_t h;
    asm("cvt.rn.f16x2.f32 %0, %1, %2;" : "=r"(h) : "f"(f1), "f"(f0));
    return h;
}
// mma.sync m16n8k16 f16 -> f32
__device__ __forceinline__ void mma16816(float c[4], const uint32_t a[4],
                                         uint32_t b0, uint32_t b1) {
    asm volatile(
        "mma.sync.aligned.m16n8k16.row.col.f32.f16.f16.f32 "
        "{%0,%1,%2,%3}, {%4,%5,%6,%7}, {%8,%9}, {%0,%1,%2,%3};"
        : "+f"(c[0]), "+f"(c[1]), "+f"(c[2]), "+f"(c[3])
        : "r"(a[0]), "r"(a[1]), "r"(a[2]), "r"(a[3]), "r"(b0), "r"(b1));
}
// stage 64x64 fp32 weight (row-major [k][n]) as f16 B-tile [n][kk] u32 words, stride 36
__device__ __forceinline__ void stage_btile(uint32_t* dst,
                                            const float* __restrict__ W, int tid, int nth) {
    for (int i = tid; i < 2048; i += nth) {
        int n = i >> 5, kk = i & 31;
        dst[n * 36 + kk] = f16_pack2(W[(2 * kk) * 64 + n], W[(2 * kk + 1) * 64 + n]);
    }
}
// 1-term K=64 mma, A from smem
__device__ __forceinline__ void mma1_smem(float acc[16][4],
                                          const uint32_t* __restrict__ Ah,
                                          const uint32_t* __restrict__ Bh,
                                          int g, int t) {
    #pragma unroll
    for (int kt = 0; kt < 4; kt++) {
        uint32_t ah[2][4];
        #pragma unroll
        for (int mt = 0; mt < 2; mt++) {
            int rb = (16 * mt + g) * 36 + 8 * kt + t;
            ah[mt][0] = Ah[rb];     ah[mt][1] = Ah[rb + 8 * 36];
            ah[mt][2] = Ah[rb + 4]; ah[mt][3] = Ah[rb + 8 * 36 + 4];
        }
        #pragma unroll
        for (int nt = 0; nt < 8; nt++) {
            int bi = (8 * nt + g) * 36 + 8 * kt + t;
            uint32_t bh0 = Bh[bi], bh1 = Bh[bi + 4];
            #pragma unroll
            for (int mt = 0; mt < 2; mt++)
                mma16816(acc[mt * 8 + nt], ah[mt], bh0, bh1);
        }
    }
}
// 1-term K=64 mma, A from register fragments
__device__ __forceinline__ void mma1_reg(float acc[16][4],
                                         const uint32_t fh[2][4][4],
                                         const uint32_t* __restrict__ Bh,
                                         int g, int t) {
    #pragma unroll
    for (int kt = 0; kt < 4; kt++) {
        #pragma unroll
        for (int nt = 0; nt < 8; nt++) {
            int bi = (8 * nt + g) * 36 + 8 * kt + t;
            uint32_t bh0 = Bh[bi], bh1 = Bh[bi + 4];
            #pragma unroll
            for (int mt = 0; mt < 2; mt++)
                mma16816(acc[mt * 8 + nt], fh[mt][kt], bh0, bh1);
        }
    }
}

// ---------- init ----------
__global__ void init_kernel(const int* __restrict__ z, const float* __restrict__ emb,
                            const float* __restrict__ t,
                            const float* __restrict__ tw1, const float* __restrict__ tb1,
                            const float* __restrict__ tw2, const float* __restrict__ tb2,
                            int B) {
    __shared__ float s1[HID];
    __shared__ float tm[HID];
    int tidb = threadIdx.x;
    if (tidb < HID) {
        float w = tw1[tidb], bb = tb1[tidb];
        float acc = 0.f;
        for (int b = 0; b < B; b++) acc += silu(t[b] * w + bb);
        s1[tidb] = acc / (float)B;
    }
    __syncthreads();
    if (tidb < HID) {
        float o = tb2[tidb];
        for (int k = 0; k < HID; k++) o += s1[k] * tw2[k * HID + tidb];
        tm[tidb] = o;
    }
    __syncthreads();
    int i = blockIdx.x * blockDim.x + tidb;
    if (i < N_NODES * HID) {
        int node = i >> 6, j = i & 63;
        g_h[i] = emb[z[node] * HID + j] + tm[j];
        g_agg[i] = 0.f;
    }
}

__global__ void dummy_kernel() {}

// ---------- pre kernel (layer 0 only): P = h@W1a + b1, Q = h@W1b ----------
#define PW_A  0
#define PW_B  2304
#define P_B1W 4608
#define P_WBASE 4672
#define P_WW 1152
#define P_SMEM_WORDS (P_WBASE + 6 * P_WW)
#define P_SMEM_BYTES (P_SMEM_WORDS * 4)   // 46,336 B

__global__ void __launch_bounds__(192)
pre_kernel(const float* __restrict__ ew1, const float* __restrict__ eb1g) {
    extern __shared__ uint32_t smw[];
    float* smf = (float*)smw;
    const int tid = threadIdx.x;

    stage_btile(smw + PW_A, ew1, tid, 192);
    stage_btile(smw + PW_B, ew1 + 64 * 64, tid, 192);
    if (tid < 64) smf[P_B1W + tid] = eb1g[tid];
    __syncthreads();

    const int lane = tid & 31;
    const int wrp = tid >> 5;
    const int g = lane >> 2;
    const int t = lane & 3;
    uint32_t* Ah = smw + P_WBASE + wrp * P_WW;

    const int gwarp = (blockIdx.x * 192 + tid) >> 5;
    const int nwarps = (gridDim.x * 192) >> 5;

    for (int grp = gwarp; grp < NODE_GROUPS; grp += nwarps) {
        const int base = grp * 32;
        __syncwarp();
        #pragma unroll 4
        for (int e2 = 0; e2 < 32; e2++) {
            float2 hv = __ldg((const float2*)(g_h + (size_t)(base + e2) * 64 + 2 * lane));
            Ah[e2 * 36 + lane] = f16_pack2(hv.x, hv.y);
        }
        __syncwarp();

        float accP[16][4], accQ[16][4];
        #pragma unroll
        for (int nt = 0; nt < 8; nt++) {
            float2 bb = *(const float2*)(smf + P_B1W + 8 * nt + 2 * t);
            #pragma unroll
            for (int mt = 0; mt < 2; mt++) {
                accP[mt * 8 + nt][0] = bb.x; accP[mt * 8 + nt][1] = bb.y;
                accP[mt * 8 + nt][2] = bb.x; accP[mt * 8 + nt][3] = bb.y;
                accQ[mt * 8 + nt][0] = 0.f; accQ[mt * 8 + nt][1] = 0.f;
                accQ[mt * 8 + nt][2] = 0.f; accQ[mt * 8 + nt][3] = 0.f;
            }
        }
        mma1_smem(accP, Ah, smw + PW_A, g, t);
        mma1_smem(accQ, Ah, smw + PW_B, g, t);
        #pragma unroll
        for (int mt = 0; mt < 2; mt++) {
            int r1 = base + 16 * mt + g;
            int r2 = r1 + 8;
            #pragma unroll
            for (int nt = 0; nt < 8; nt++) {
                int c = 8 * nt + 2 * t;
                *(float2*)(g_P + (size_t)r1 * 64 + c) = make_float2(accP[mt * 8 + nt][0], accP[mt * 8 + nt][1]);
                *(float2*)(g_P + (size_t)r2 * 64 + c) = make_float2(accP[mt * 8 + nt][2], accP[mt * 8 + nt][3]);
                *(float2*)(g_Q + (size_t)r1 * 64 + c) = make_float2(accQ[mt * 8 + nt][0], accQ[mt * 8 + nt][1]);
                *(float2*)(g_Q + (size_t)r2 * 64 + c) = make_float2(accQ[mt * 8 + nt][2], accQ[mt * 8 + nt][3]);
            }
        }
    }
}

// ---------- edge kernel (fp16 1-term, 4 CTAs/SM) ----------
#define B_W2H  0
#define B_C1H  2304
#define SC_W1C 4608
#define SC_B2  4672
#define SC_CB1 4736
#define SC_CW2 4800
#define SC_CB2 4864
#define WARP_BASE 4868
#define WARP_W 1152
#define EDGE_SMEM_WORDS (WARP_BASE + 4 * WARP_W)
#define EDGE_SMEM_BYTES (EDGE_SMEM_WORDS * 4)   // 37,904 B -> 4 CTAs/SM

__global__ void __launch_bounds__(128, 4)
edge_kernel(const float* __restrict__ x, float* __restrict__ xn,
            const int* __restrict__ ei,
            const float* __restrict__ w1c_g,
            const float* __restrict__ ew2, const float* __restrict__ eb2g,
            const float* __restrict__ cw1, const float* __restrict__ cb1g,
            const float* __restrict__ cw2g, const float* __restrict__ cb2g,
            int do_agg) {
    extern __shared__ uint32_t smw[];
    float* smf = (float*)smw;
    const int tid = threadIdx.x;

    stage_btile(smw + B_W2H, ew2, tid, 128);
    stage_btile(smw + B_C1H, cw1, tid, 128);
    if (tid < 64) {
        smf[SC_W1C + tid] = w1c_g[tid];
        smf[SC_B2 + tid]  = eb2g[tid];
        smf[SC_CB1 + tid] = cb1g[tid];
        smf[SC_CW2 + tid] = cw2g[tid];
    }
    if (tid == 0) smf[SC_CB2] = cb2g[0];
    __syncthreads();

    const int lane = tid & 31;
    const int wrp = tid >> 5;
    const int g = lane >> 2;
    const int t = lane & 3;
    uint32_t* Ah = smw + WARP_BASE + wrp * WARP_W;
    const float w1c0 = smf[SC_W1C + 2 * lane];
    const float w1c1 = smf[SC_W1C + 2 * lane + 1];
    const float cb2s = smf[SC_CB2];

    const int gwarp = (blockIdx.x * 128 + tid) >> 5;
    const int nwarps = (gridDim.x * 128) >> 5;

    int grp = gwarp;
    int s_n = 0, d_n = 0;
    float xs0 = 0, xs1 = 0, xs2 = 0, xd0 = 0, xd1 = 0, xd2 = 0;
    if (grp < NGROUPS) {
        int e = grp * 32 + lane;
        s_n = ei[e]; d_n = ei[N_EDGES + e];
        xs0 = __ldg(&x[s_n * 3 + 0]); xs1 = __ldg(&x[s_n * 3 + 1]); xs2 = __ldg(&x[s_n * 3 + 2]);
        xd0 = __ldg(&x[d_n * 3 + 0]); xd1 = __ldg(&x[d_n * 3 + 1]); xd2 = __ldg(&x[d_n * 3 + 2]);
    }

    for (; grp < NGROUPS; grp += nwarps) {
        const int s = s_n, d = d_n;
        const float dx0 = xd0 - xs0;
        const float dx1 = xd1 - xs1;
        const float dx2 = xd2 - xs2;
        const float r2 = dx0 * dx0 + dx1 * dx1 + dx2 * dx2;

        // ---- gather + phase1 fused (indices via shfl) ----
        __syncwarp();
        #pragma unroll 4
        for (int e2 = 0; e2 < 32; e2++) {
            int nd = __shfl_sync(0xffffffffu, d, e2);
            int ns = __shfl_sync(0xffffffffu, s, e2);
            float rr = __shfl_sync(0xffffffffu, r2, e2);
            float2 pv = __ldg((const float2*)(g_P + (size_t)nd * 64 + 2 * lane));
            float2 qv = __ldg((const float2*)(g_Q + (size_t)ns * 64 + 2 * lane));
            float f0 = silu(fmaf(rr, w1c0, pv.x + qv.x));
            float f1 = silu(fmaf(rr, w1c1, pv.y + qv.y));
            Ah[e2 * 36 + lane] = f16_pack2(f0, f1);
        }
        __syncwarp();

        // ---- prefetch next group ----
        {
            int gn = grp + nwarps;
            if (gn < NGROUPS) {
                int e = gn * 32 + lane;
                s_n = ei[e]; d_n = ei[N_EDGES + e];
                xs0 = __ldg(&x[s_n * 3 + 0]); xs1 = __ldg(&x[s_n * 3 + 1]); xs2 = __ldg(&x[s_n * 3 + 2]);
                xd0 = __ldg(&x[d_n * 3 + 0]); xd1 = __ldg(&x[d_n * 3 + 1]); xd2 = __ldg(&x[d_n * 3 + 2]);
            }
        }

        // ---- matmul1: D = ef1 @ W2 + b2 ----
        float acc[16][4];
        #pragma unroll
        for (int nt = 0; nt < 8; nt++) {
            float2 bb = *(const float2*)(smf + SC_B2 + 8 * nt + 2 * t);
            #pragma unroll
            for (int mt = 0; mt < 2; mt++) {
                acc[mt * 8 + nt][0] = bb.x; acc[mt * 8 + nt][1] = bb.y;
                acc[mt * 8 + nt][2] = bb.x; acc[mt * 8 + nt][3] = bb.y;
            }
        }
        mma1_smem(acc, Ah, smw + B_W2H, g, t);

        // ---- m = silu(D); paired red.v4; pack to matmul2 A frags ----
        uint32_t mh[2][4][4];
        int dtop[2], dbot[2];
        #pragma unroll
        for (int mt = 0; mt < 2; mt++) {
            dtop[mt] = __shfl_sync(0xffffffffu, d, 16 * mt + g);
            dbot[mt] = __shfl_sync(0xffffffffu, d, 16 * mt + g + 8);
        }
        const int colbase_off = 2 * (t & ~1);
        #pragma unroll
        for (int mt = 0; mt < 2; mt++) {
            #pragma unroll
            for (int nt = 0; nt < 8; nt++) {
                float v0 = silu(acc[mt * 8 + nt][0]);
                float v1 = silu(acc[mt * 8 + nt][1]);
                float v2 = silu(acc[mt * 8 + nt][2]);
                float v3 = silu(acc[mt * 8 + nt][3]);
                if (do_agg) {
                    float px = (t & 1) ? v0 : v2;
                    float qx = (t & 1) ? v1 : v3;
                    float pr = __shfl_xor_sync(0xffffffffu, px, 1);
                    float qr = __shfl_xor_sync(0xffffffffu, qx, 1);
                    int row = (t & 1) ? dbot[mt] : dtop[mt];
                    int col = 8 * nt + colbase_off;
                    float a0 = (t & 1) ? pr : v0;
                    float a1 = (t & 1) ? qr : v1;
                    float a2 = (t & 1) ? v2 : pr;
                    float a3 = (t & 1) ? v3 : qr;
                    red_add_v4(&g_agg[(size_t)row * 64 + col], a0, a1, a2, a3);
                }
                int kt = nt >> 1, o = (nt & 1) * 2;
                mh[mt][kt][o]     = f16_pack2(v0, v1);
                mh[mt][kt][o + 1] = f16_pack2(v2, v3);
            }
        }

        // ---- matmul2: D2 = m @ C1 + cb1 ----
        float acc2[16][4];
        #pragma unroll
        for (int nt = 0; nt < 8; nt++) {
            float2 bb = *(const float2*)(smf + SC_CB1 + 8 * nt + 2 * t);
            #pragma unroll
            for (int mt = 0; mt < 2; mt++) {
                acc2[mt * 8 + nt][0] = bb.x; acc2[mt * 8 + nt][1] = bb.y;
                acc2[mt * 8 + nt][2] = bb.x; acc2[mt * 8 + nt][3] = bb.y;
            }
        }
        mma1_reg(acc2, mh, smw + B_C1H, g, t);

        // ---- coord epilogue ----
        float pr0 = 0.f, pr1 = 0.f, pr2 = 0.f, pr3 = 0.f;
        #pragma unroll
        for (int nt = 0; nt < 8; nt++) {
            float2 cwv = *(const float2*)(smf + SC_CW2 + 8 * nt + 2 * t);
            pr0 = fmaf(silu(acc2[nt][0]), cwv.x, pr0);
            pr0 = fmaf(silu(acc2[nt][1]), cwv.y, pr0);
            pr1 = fmaf(silu(acc2[nt][2]), cwv.x, pr1);
            pr1 = fmaf(silu(acc2[nt][3]), cwv.y, pr1);
            pr2 = fmaf(silu(acc2[8 + nt][0]), cwv.x, pr2);
            pr2 = fmaf(silu(acc2[8 + nt][1]), cwv.y, pr2);
            pr3 = fmaf(silu(acc2[8 + nt][2]), cwv.x, pr3);
            pr3 = fmaf(silu(acc2[8 + nt][3]), cwv.y, pr3);
        }
        pr0 += __shfl_xor_sync(0xffffffffu, pr0, 1);
        pr0 += __shfl_xor_sync(0xffffffffu, pr0, 2);
        pr1 += __shfl_xor_sync(0xffffffffu, pr1, 1);
        pr1 += __shfl_xor_sync(0xffffffffu, pr1, 2);
        pr2 += __shfl_xor_sync(0xffffffffu, pr2, 1);
        pr2 += __shfl_xor_sync(0xffffffffu, pr2, 2);
        pr3 += __shfl_xor_sync(0xffffffffu, pr3, 1);
        pr3 += __shfl_xor_sync(0xffffffffu, pr3, 2);
        float p = (t == 0) ? pr0 : (t == 1) ? pr1 : (t == 2) ? pr2 : pr3;
        const int e2l = g + 8 * t;
        p += cb2s;
        int dd = __shfl_sync(0xffffffffu, d, e2l);
        float ddx0 = __shfl_sync(0xffffffffu, dx0, e2l);
        float ddx1 = __shfl_sync(0xffffffffu, dx1, e2l);
        float ddx2 = __shfl_sync(0xffffffffu, dx2, e2l);
        atomicAdd(&xn[dd * 3 + 0], ddx0 * p);
        atomicAdd(&xn[dd * 3 + 1], ddx1 * p);
        atomicAdd(&xn[dd * 3 + 2], ddx2 * p);
    }
}

// ---------- node kernel (fp16 1-term) + fused next-layer P/Q ----------
#define N_W1H  0
#define N_W1A  2304
#define N_W2   4608
#define N_PA   6912
#define N_PB   9216
#define N_B1W  11520
#define N_B2W  11584
#define N_EB1W 11648
#define N_ABASE 11712
#define N_AW   1152
#define NODE_SMEM_WORDS (N_ABASE + 12 * N_AW)
#define NODE_SMEM_BYTES (NODE_SMEM_WORDS * 4)   // 102,144 B -> 1 CTA/SM at 384 thr

__global__ void __launch_bounds__(384)
node_kernel(const float* __restrict__ nw1, const float* __restrict__ nb1g,
            const float* __restrict__ nw2, const float* __restrict__ nb2g,
            const float* __restrict__ ew1n, const float* __restrict__ eb1n) {
    extern __shared__ uint32_t smw[];
    float* smf = (float*)smw;
    const int tid = threadIdx.x;

    stage_btile(smw + N_W1H, nw1, tid, 384);
    stage_btile(smw + N_W1A, nw1 + 64 * 64, tid, 384);
    stage_btile(smw + N_W2, nw2, tid, 384);
    stage_btile(smw + N_PA, ew1n, tid, 384);
    stage_btile(smw + N_PB, ew1n + 64 * 64, tid, 384);
    if (tid < 64) {
        smf[N_B1W + tid]  = nb1g[tid];
        smf[N_B2W + tid]  = nb2g[tid];
        smf[N_EB1W + tid] = eb1n[tid];
    }
    __syncthreads();

    const int lane = tid & 31;
    const int wrp = tid >> 5;
    const int g = lane >> 2;
    const int t = lane & 3;
    uint32_t* Ah = smw + N_ABASE + wrp * N_AW;

    const int gwarp = (blockIdx.x * 384 + tid) >> 5;
    const int nwarps = (gridDim.x * 384) >> 5;

    for (int grp = gwarp; grp < NODE_GROUPS; grp += nwarps) {
        const int base = grp * 32;

        // ---- gather h -> A frags ----
        __syncwarp();
        #pragma unroll 4
        for (int e2 = 0; e2 < 32; e2++) {
            float2 hv = __ldg((const float2*)(g_h + (size_t)(base + e2) * 64 + 2 * lane));
            Ah[e2 * 36 + lane] = f16_pack2(hv.x, hv.y);
        }
        __syncwarp();

        float acc1[16][4];
        #pragma unroll
        for (int nt = 0; nt < 8; nt++) {
            float2 bb = *(const float2*)(smf + N_B1W + 8 * nt + 2 * t);
            #pragma unroll
            for (int mt = 0; mt < 2; mt++) {
                acc1[mt * 8 + nt][0] = bb.x; acc1[mt * 8 + nt][1] = bb.y;
                acc1[mt * 8 + nt][2] = bb.x; acc1[mt * 8 + nt][3] = bb.y;
            }
        }
        mma1_smem(acc1, Ah, smw + N_W1H, g, t);

        // ---- gather agg (and zero it); accumulate @ W1agg ----
        __syncwarp();
        #pragma unroll 4
        for (int e2 = 0; e2 < 32; e2++) {
            float2* ap = (float2*)(g_agg + (size_t)(base + e2) * 64 + 2 * lane);
            float2 av = *ap;
            *ap = make_float2(0.f, 0.f);
            Ah[e2 * 36 + lane] = f16_pack2(av.x, av.y);
        }
        __syncwarp();
        mma1_smem(acc1, Ah, smw + N_W1A, g, t);

        // ---- hid = silu(acc1) -> register A frags ----
        uint32_t mh[2][4][4];
        #pragma unroll
        for (int mt = 0; mt < 2; mt++) {
            #pragma unroll
            for (int nt = 0; nt < 8; nt++) {
                float v0 = silu(acc1[mt * 8 + nt][0]);
                float v1 = silu(acc1[mt * 8 + nt][1]);
                float v2 = silu(acc1[mt * 8 + nt][2]);
                float v3 = silu(acc1[mt * 8 + nt][3]);
                int kt = nt >> 1, o = (nt & 1) * 2;
                mh[mt][kt][o]     = f16_pack2(v0, v1);
                mh[mt][kt][o + 1] = f16_pack2(v2, v3);
            }
        }

        // ---- acc2 = hid @ W2 + b2; h_new = h_old + acc2 ----
        float acc2[16][4];
        #pragma unroll
        for (int nt = 0; nt < 8; nt++) {
            float2 bb = *(const float2*)(smf + N_B2W + 8 * nt + 2 * t);
            #pragma unroll
            for (int mt = 0; mt < 2; mt++) {
                acc2[mt * 8 + nt][0] = bb.x; acc2[mt * 8 + nt][1] = bb.y;
                acc2[mt * 8 + nt][2] = bb.x; acc2[mt * 8 + nt][3] = bb.y;
            }
        }
        mma1_reg(acc2, mh, smw + N_W2, g, t);

        // residual + writeback + pack h_new frags
        uint32_t hh[2][4][4];
        #pragma unroll
        for (int mt = 0; mt < 2; mt++) {
            int r1 = base + 16 * mt + g;
            int r2 = r1 + 8;
            #pragma unroll
            for (int nt = 0; nt < 8; nt++) {
                int c = 8 * nt + 2 * t;
                float2 h1 = __ldg((const float2*)(g_h + (size_t)r1 * 64 + c));
                float2 h2 = __ldg((const float2*)(g_h + (size_t)r2 * 64 + c));
                float v0 = h1.x + acc2[mt * 8 + nt][0];
                float v1 = h1.y + acc2[mt * 8 + nt][1];
                float v2 = h2.x + acc2[mt * 8 + nt][2];
                float v3 = h2.y + acc2[mt * 8 + nt][3];
                *(float2*)(g_h + (size_t)r1 * 64 + c) = make_float2(v0, v1);
                *(float2*)(g_h + (size_t)r2 * 64 + c) = make_float2(v2, v3);
                int kt = nt >> 1, o = (nt & 1) * 2;
                hh[mt][kt][o]     = f16_pack2(v0, v1);
                hh[mt][kt][o + 1] = f16_pack2(v2, v3);
            }
        }

        // ---- P = h_new @ W1a' + b1' ----
        float accp[16][4];
        #pragma unroll
        for (int nt = 0; nt < 8; nt++) {
            float2 bb = *(const float2*)(smf + N_EB1W + 8 * nt + 2 * t);
            #pragma unroll
            for (int mt = 0; mt < 2; mt++) {
                accp[mt * 8 + nt][0] = bb.x; accp[mt * 8 + nt][1] = bb.y;
                accp[mt * 8 + nt][2] = bb.x; accp[mt * 8 + nt][3] = bb.y;
            }
        }
        mma1_reg(accp, hh, smw + N_PA, g, t);
        #pragma unroll
        for (int mt = 0; mt < 2; mt++) {
            int r1 = base + 16 * mt + g;
            int r2 = r1 + 8;
            #pragma unroll
            for (int nt = 0; nt < 8; nt++) {
                int c = 8 * nt + 2 * t;
                *(float2*)(g_P + (size_t)r1 * 64 + c) = make_float2(accp[mt * 8 + nt][0], accp[mt * 8 + nt][1]);
                *(float2*)(g_P + (size_t)r2 * 64 + c) = make_float2(accp[mt * 8 + nt][2], accp[mt * 8 + nt][3]);
            }
        }

        // ---- Q = h_new @ W1b' ----
        #pragma unroll
        for (int a = 0; a < 16; a++) {
            accp[a][0] = 0.f; accp[a][1] = 0.f; accp[a][2] = 0.f; accp[a][3] = 0.f;
        }
        mma1_reg(accp, hh, smw + N_PB, g, t);
        #pragma unroll
        for (int mt = 0; mt < 2; mt++) {
            int r1 = base + 16 * mt + g;
            int r2 = r1 + 8;
            #pragma unroll
            for (int nt = 0; nt < 8; nt++) {
                int c = 8 * nt + 2 * t;
                *(float2*)(g_Q + (size_t)r1 * 64 + c) = make_float2(accp[mt * 8 + nt][0], accp[mt * 8 + nt][1]);
                *(float2*)(g_Q + (size_t)r2 * 64 + c) = make_float2(accp[mt * 8 + nt][2], accp[mt * 8 + nt][3]);
            }
        }
    }
}

// ---------- launch ----------
extern "C" void kernel_launch(void* const* d_in, const int* in_sizes, int n_in,
                              void* d_out, int out_size) {
    const float* x   = (const float*)d_in[0];
    const int*   z   = (const int*)d_in[1];
    const float* t   = (const float*)d_in[2];
    const int*   ei  = (const int*)d_in[3];
    const float* emb = (const float*)d_in[4];
    const float* tw1 = (const float*)d_in[5];
    const float* tb1 = (const float*)d_in[6];
    const float* tw2 = (const float*)d_in[7];
    const float* tb2 = (const float*)d_in[8];
    const float* ew1 = (const float*)d_in[9];
    const float* eb1 = (const float*)d_in[10];
    const float* ew2 = (const float*)d_in[11];
    const float* eb2 = (const float*)d_in[12];
    const float* cw1 = (const float*)d_in[13];
    const float* cb1 = (const float*)d_in[14];
    const float* cw2 = (const float*)d_in[15];
    const float* cb2 = (const float*)d_in[16];
    const float* nw1 = (const float*)d_in[17];
    const float* nb1 = (const float*)d_in[18];
    const float* nw2 = (const float*)d_in[19];
    const float* nb2 = (const float*)d_in[20];
    float* out = (float*)d_out;
    const int B = in_sizes[2];

    float *pxA, *pxB;
    cudaGetSymbolAddress((void**)&pxA, g_xA);
    cudaGetSymbolAddress((void**)&pxB, g_xB);

    cudaFuncSetAttribute(edge_kernel, cudaFuncAttributeMaxDynamicSharedMemorySize, EDGE_SMEM_BYTES);
    cudaFuncSetAttribute(node_kernel, cudaFuncAttributeMaxDynamicSharedMemorySize, NODE_SMEM_BYTES);
    cudaFuncSetAttribute(pre_kernel,  cudaFuncAttributeMaxDynamicSharedMemorySize, P_SMEM_BYTES);

    const size_t XB = (size_t)N_NODES * 3 * sizeof(float);
    const int EGRID = 608;   // 4 CTAs/SM x 152

    // launches: 0 init, 1 pre, 2 edge0, 3 node0, 4 dummy, 5 edge1 (ncu -s 5 target)
    init_kernel<<<(N_NODES * HID + 255) / 256, 256>>>(z, emb, t, tw1, tb1, tw2, tb2, B);

    // ---- layer 0 ----
    pre_kernel<<<304, 192, P_SMEM_BYTES>>>(ew1 + 0 * 129 * 64, eb1 + 0 * 64);
    cudaMemcpyAsync(pxB, x, XB, cudaMemcpyDeviceToDevice, 0);
    edge_kernel<<<EGRID, 128, EDGE_SMEM_BYTES>>>(x, pxB, ei,
        ew1 + 0 * 129 * 64 + 128 * 64, ew2 + 0 * 4096, eb2 + 0 * 64,
        cw1 + 0 * 4096, cb1 + 0 * 64, cw2 + 0 * 64, cb2 + 0, 1);
    node_kernel<<<152, 384, NODE_SMEM_BYTES>>>(nw1 + 0 * 128 * 64, nb1 + 0 * 64,
                                               nw2 + 0 * 4096, nb2 + 0 * 64,
                                               ew1 + 1 * 129 * 64, eb1 + 1 * 64);
    dummy_kernel<<<1, 32>>>();

    // ---- layer 1 ----
    cudaMemcpyAsync(pxA, pxB, XB, cudaMemcpyDeviceToDevice, 0);
    edge_kernel<<<EGRID, 128, EDGE_SMEM_BYTES>>>(pxB, pxA, ei,
        ew1 + 1 * 129 * 64 + 128 * 64, ew2 + 1 * 4096, eb2 + 1 * 64,
        cw1 + 1 * 4096, cb1 + 1 * 64, cw2 + 1 * 64, cb2 + 1, 1);
    node_kernel<<<152, 384, NODE_SMEM_BYTES>>>(nw1 + 1 * 128 * 64, nb1 + 1 * 64,
                                               nw2 + 1 * 4096, nb2 + 1 * 64,
                                               ew1 + 2 * 129 * 64, eb1 + 2 * 64);

    // ---- layer 2: agg/node dead, write x' straight to d_out ----
    cudaMemcpyAsync(out, pxA, XB, cudaMemcpyDeviceToDevice, 0);
    edge_kernel<<<EGRID, 128, EDGE_SMEM_BYTES>>>(pxA, out, ei,
        ew1 + 2 * 129 * 64 + 128 * 64, ew2 + 2 * 4096, eb2 + 2 * 64,
        cw1 + 2 * 4096, cb1 + 2 * 64, cw2 + 2 * 64, cb2 + 2, 0);
}